// round 8
// baseline (speedup 1.0000x reference)
#include <cuda_runtime.h>
#include <math.h>
#include <stdint.h>

// ---------------------------------------------------------------------------
// Problem dimensions
// ---------------------------------------------------------------------------
#define SQ   2048
#define HDIM 1024
#define NH   16
#define HD   64
#define ISZ  4096

// ---------------------------------------------------------------------------
// Scratch
// ---------------------------------------------------------------------------
__device__ float g_xn [SQ * HDIM];
__device__ float g_q  [SQ * HDIM];
__device__ float g_k  [SQ * HDIM];
__device__ float g_v  [SQ * HDIM];
__device__ float g_att[SQ * HDIM];
__device__ float g_h1 [SQ * HDIM];
__device__ float g_h2 [SQ * HDIM];
__device__ float g_gate[SQ * ISZ];
__device__ float g_up  [SQ * ISZ];
__device__ float g_gu  [SQ * ISZ];

// ---------------------------------------------------------------------------
// Helpers (Ampere-era instructions only: proven to compile on this harness)
// ---------------------------------------------------------------------------
__device__ __forceinline__ uint32_t f2tf(float f) {
    uint32_t r;
    asm("cvt.rna.tf32.f32 %0, %1;" : "=r"(r) : "f"(f));
    return r;
}

__device__ __forceinline__ void mma_tf32(float* c, const uint32_t* a,
                                         uint32_t b0, uint32_t b1) {
    asm volatile(
        "mma.sync.aligned.m16n8k8.row.col.f32.tf32.tf32.f32 "
        "{%0,%1,%2,%3}, {%4,%5,%6,%7}, {%8,%9}, {%0,%1,%2,%3};"
        : "+f"(c[0]), "+f"(c[1]), "+f"(c[2]), "+f"(c[3])
        : "r"(a[0]), "r"(a[1]), "r"(a[2]), "r"(a[3]), "r"(b0), "r"(b1));
}

__device__ __forceinline__ void cp16(uint32_t smem_dst, const void* gsrc) {
    asm volatile("cp.async.ca.shared.global [%0], [%1], 16;\n"
                 :: "r"(smem_dst), "l"(gsrc));
}
__device__ __forceinline__ void cp_commit() {
    asm volatile("cp.async.commit_group;\n" ::: "memory");
}
template <int N>
__device__ __forceinline__ void cp_wait() {
    asm volatile("cp.async.wait_group %0;\n" :: "n"(N) : "memory");
}

// ---------------------------------------------------------------------------
// RMSNorm
// ---------------------------------------------------------------------------
__global__ void __launch_bounds__(256) rmsnorm_kernel(
    const float* __restrict__ x, const float* __restrict__ w,
    float* __restrict__ y)
{
    const int row = blockIdx.x;
    const int t   = threadIdx.x;
    float4 vx = ((const float4*)(x + (size_t)row * HDIM))[t];
    float s = vx.x*vx.x + vx.y*vx.y + vx.z*vx.z + vx.w*vx.w;
    #pragma unroll
    for (int o = 16; o; o >>= 1) s += __shfl_xor_sync(0xffffffffu, s, o);

    __shared__ float red[8];
    __shared__ float s_inv;
    if ((t & 31) == 0) red[t >> 5] = s;
    __syncthreads();
    if (t == 0) {
        float tot = 0.f;
        #pragma unroll
        for (int i = 0; i < 8; ++i) tot += red[i];
        s_inv = 1.0f / sqrtf(tot * (1.0f / (float)HDIM) + 1e-6f);
    }
    __syncthreads();
    const float r = s_inv;
    float4 vw = ((const float4*)w)[t];
    float4 o4 = make_float4(vx.x*r*vw.x, vx.y*r*vw.y, vx.z*r*vw.z, vx.w*r*vw.w);
    ((float4*)(y + (size_t)row * HDIM))[t] = o4;
}

// ---------------------------------------------------------------------------
// tf32 mma.sync GEMM, 3-stage cp.async pipeline, full fragment hoisting.
// C[M,N] = A[M,K] @ B[K,N] (+R), row-major. BM=128, BN=64, BK=32.
// 8 warps (4m x 2n), warp tile 32x32. blockIdx.z: fused siblings.
// NOTE: cp_commit() is called UNCONDITIONALLY every iteration (empty groups
// in the tail) so cp.async group accounting proves the last tiles resident.
// ---------------------------------------------------------------------------
#define GA_LD 36                 // 32+4: conflict-free A fragment loads
#define GB_LD 68                 // 64+4
#define A_STG (128 * GA_LD)      // words per A stage
#define B_STG (32 * GB_LD)       // words per B stage
#define GEMM_SMEM ((3 * A_STG + 3 * B_STG) * 4)

__global__ void __launch_bounds__(256) gemm_tf32_kernel(
    const float* __restrict__ A,
    const float* __restrict__ B0, const float* __restrict__ B1,
    const float* __restrict__ B2,
    const float* __restrict__ R,
    float* __restrict__ C0, float* __restrict__ C1, float* __restrict__ C2,
    int M, int N, int K)
{
    extern __shared__ uint32_t smw[];
    uint32_t* As = smw;              // [3][A_STG]
    uint32_t* Bs = smw + 3 * A_STG;  // [3][B_STG]

    const float* B = (blockIdx.z == 0) ? B0 : (blockIdx.z == 1 ? B1 : B2);
    float*       C = (blockIdx.z == 0) ? C0 : (blockIdx.z == 1 ? C1 : C2);

    const int tid  = threadIdx.x;
    const int lane = tid & 31;
    const int wid  = tid >> 5;
    const int g    = lane >> 2;
    const int tig  = lane & 3;
    const int wm   = (wid >> 1) * 32;
    const int wn   = (wid & 1) * 32;
    const int bm   = blockIdx.y * 128;
    const int bn   = blockIdx.x * 64;

    float acc[2][4][4];
    #pragma unroll
    for (int mt = 0; mt < 2; ++mt)
        #pragma unroll
        for (int nt = 0; nt < 4; ++nt)
            #pragma unroll
            for (int e = 0; e < 4; ++e) acc[mt][nt][e] = 0.f;

    const int niter = K >> 5;   // BK = 32

    auto issue = [&](int i, int s) {
        const int k0 = i << 5;
        // A tile 128x32 floats = 1024 16B-chunks / 256 threads = 4 each
        #pragma unroll
        for (int it = 0; it < 4; ++it) {
            const int chunk = tid + it * 256;
            const int r = chunk >> 3;
            const int j = (chunk & 7) << 2;
            uint32_t dst = (uint32_t)__cvta_generic_to_shared(
                &As[s * A_STG + r * GA_LD + j]);
            cp16(dst, A + (size_t)(bm + r) * K + k0 + j);
        }
        // B tile 32x64 floats = 512 chunks / 256 threads = 2 each
        #pragma unroll
        for (int it = 0; it < 2; ++it) {
            const int chunk = tid + it * 256;
            const int r = chunk >> 4;
            const int c = (chunk & 15) << 2;
            uint32_t dst = (uint32_t)__cvta_generic_to_shared(
                &Bs[s * B_STG + r * GB_LD + c]);
            cp16(dst, B + (size_t)(k0 + r) * N + bn + c);
        }
    };

    issue(0, 0);
    cp_commit();                     // G0 = tile 0
    if (niter > 1) issue(1, 1);
    cp_commit();                     // G1 = tile 1 (or empty)

    for (int i = 0; i < niter; ++i) {
        const int s = i - (i / 3) * 3;          // i % 3
        cp_wait<1>();                            // G0..Gi complete -> tile i resident
        __syncthreads();

        // ---- Load ALL fragments for this K-tile (independent LDS, MLP) ----
        uint32_t bf[4][4][2];
        uint32_t af[4][2][4];
        const uint32_t* Bst = Bs + s * B_STG;
        const uint32_t* Ast = As + s * A_STG;
        #pragma unroll
        for (int kt = 0; kt < 4; ++kt) {
            #pragma unroll
            for (int nt = 0; nt < 4; ++nt) {
                const int n = wn + nt * 8 + g;
                bf[kt][nt][0] = Bst[(kt * 8 + tig)     * GB_LD + n];
                bf[kt][nt][1] = Bst[(kt * 8 + tig + 4) * GB_LD + n];
            }
            #pragma unroll
            for (int mt = 0; mt < 2; ++mt) {
                const int base = (wm + mt * 16 + g) * GA_LD + kt * 8 + tig;
                af[kt][mt][0] = Ast[base];
                af[kt][mt][1] = Ast[base + 8 * GA_LD];
                af[kt][mt][2] = Ast[base + 4];
                af[kt][mt][3] = Ast[base + 8 * GA_LD + 4];
            }
        }

        // ---- Issue all 32 MMAs (8 independent accumulator chains) ----
        #pragma unroll
        for (int kt = 0; kt < 4; ++kt)
            #pragma unroll
            for (int mt = 0; mt < 2; ++mt)
                #pragma unroll
                for (int nt = 0; nt < 4; ++nt)
                    mma_tf32(acc[mt][nt], af[kt][mt],
                             bf[kt][nt][0], bf[kt][nt][1]);

        __syncthreads();   // stage (i+2)%3's previous consumers are done
        const int j = i + 2;
        if (j < niter) issue(j, j - (j / 3) * 3);
        cp_commit();       // UNCONDITIONAL: G(i+2), empty in the tail
    }

    // Epilogue
    #pragma unroll
    for (int mt = 0; mt < 2; ++mt) {
        const int r0 = bm + wm + mt * 16 + g;
        const int r1 = r0 + 8;
        #pragma unroll
        for (int nt = 0; nt < 4; ++nt) {
            const int col = bn + wn + nt * 8 + 2 * tig;
            float2 v0 = make_float2(acc[mt][nt][0], acc[mt][nt][1]);
            float2 v1 = make_float2(acc[mt][nt][2], acc[mt][nt][3]);
            if (R) {
                float2 a0 = *(const float2*)(R + (size_t)r0 * N + col);
                float2 a1 = *(const float2*)(R + (size_t)r1 * N + col);
                v0.x += a0.x; v0.y += a0.y;
                v1.x += a1.x; v1.y += a1.y;
            }
            *(float2*)(C + (size_t)r0 * N + col) = v0;
            *(float2*)(C + (size_t)r1 * N + col) = v1;
        }
    }
}

// ---------------------------------------------------------------------------
// Flash attention with tf32 mma.sync (proven correct, unchanged)
// ---------------------------------------------------------------------------
#define AQ_LD 68
#define AV_LD 67
#define ATT_SMEM ((128 * AQ_LD + 64 * AQ_LD + 64 * AV_LD) * 4)

__global__ void __launch_bounds__(256) attn_tc_kernel(
    const float* __restrict__ Qg, const float* __restrict__ Kg,
    const float* __restrict__ Vg, float* __restrict__ Og)
{
    extern __shared__ uint32_t sm[];
    uint32_t* Qs = sm;
    uint32_t* Ks = sm + 128 * AQ_LD;
    uint32_t* Vt = sm + 128 * AQ_LD + 64 * AQ_LD;

    const int tid  = threadIdx.x;
    const int lane = tid & 31;
    const int wid  = tid >> 5;
    const int g    = lane >> 2;
    const int tig  = lane & 3;
    const int i0   = blockIdx.x * 128;
    const int hoff = blockIdx.y * HD;
    const int qrow = wid * 16;

    {
        const float scale = 0.125f;
        #pragma unroll
        for (int it = 0; it < 8; ++it) {
            const int r  = it * 16 + (tid >> 4);
            const int c4 = (tid & 15) << 2;
            float4 v = *(const float4*)(Qg + (size_t)(i0 + r) * HDIM + hoff + c4);
            Qs[r * AQ_LD + c4 + 0] = f2tf(v.x * scale);
            Qs[r * AQ_LD + c4 + 1] = f2tf(v.y * scale);
            Qs[r * AQ_LD + c4 + 2] = f2tf(v.z * scale);
            Qs[r * AQ_LD + c4 + 3] = f2tf(v.w * scale);
        }
    }

    float m0 = -1e30f, m1 = -1e30f;
    float l0 = 0.f, l1 = 0.f;
    float o[8][4];
    #pragma unroll
    for (int nt = 0; nt < 8; ++nt)
        #pragma unroll
        for (int e = 0; e < 4; ++e) o[nt][e] = 0.f;

    for (int j0 = 0; j0 < SQ; j0 += 64) {
        __syncthreads();
        #pragma unroll
        for (int it = 0; it < 4; ++it) {
            const int r  = it * 16 + (tid >> 4);
            const int c4 = (tid & 15) << 2;
            float4 kv = *(const float4*)(Kg + (size_t)(j0 + r) * HDIM + hoff + c4);
            Ks[r * AQ_LD + c4 + 0] = f2tf(kv.x);
            Ks[r * AQ_LD + c4 + 1] = f2tf(kv.y);
            Ks[r * AQ_LD + c4 + 2] = f2tf(kv.z);
            Ks[r * AQ_LD + c4 + 3] = f2tf(kv.w);
            float4 vv = *(const float4*)(Vg + (size_t)(j0 + r) * HDIM + hoff + c4);
            Vt[(c4 + 0) * AV_LD + r] = f2tf(vv.x);
            Vt[(c4 + 1) * AV_LD + r] = f2tf(vv.y);
            Vt[(c4 + 2) * AV_LD + r] = f2tf(vv.z);
            Vt[(c4 + 3) * AV_LD + r] = f2tf(vv.w);
        }
        __syncthreads();

        float s[8][4];
        #pragma unroll
        for (int nt = 0; nt < 8; ++nt)
            #pragma unroll
            for (int e = 0; e < 4; ++e) s[nt][e] = 0.f;

        #pragma unroll
        for (int kt = 0; kt < 8; ++kt) {
            uint32_t a[4];
            const int base = (qrow + g) * AQ_LD + kt * 8 + tig;
            a[0] = Qs[base];
            a[1] = Qs[base + 8 * AQ_LD];
            a[2] = Qs[base + 4];
            a[3] = Qs[base + 8 * AQ_LD + 4];
            #pragma unroll
            for (int nt = 0; nt < 8; ++nt) {
                const int jb = (nt * 8 + g) * AQ_LD + kt * 8 + tig;
                mma_tf32(s[nt], a, Ks[jb], Ks[jb + 4]);
            }
        }

        float mt0 = -1e30f, mt1 = -1e30f;
        #pragma unroll
        for (int nt = 0; nt < 8; ++nt) {
            mt0 = fmaxf(mt0, fmaxf(s[nt][0], s[nt][1]));
            mt1 = fmaxf(mt1, fmaxf(s[nt][2], s[nt][3]));
        }
        mt0 = fmaxf(mt0, __shfl_xor_sync(0xffffffffu, mt0, 1));
        mt0 = fmaxf(mt0, __shfl_xor_sync(0xffffffffu, mt0, 2));
        mt1 = fmaxf(mt1, __shfl_xor_sync(0xffffffffu, mt1, 1));
        mt1 = fmaxf(mt1, __shfl_xor_sync(0xffffffffu, mt1, 2));

        const float mn0 = fmaxf(m0, mt0);
        const float mn1 = fmaxf(m1, mt1);
        const float c0 = __expf(m0 - mn0);
        const float c1 = __expf(m1 - mn1);
        m0 = mn0; m1 = mn1;

        float ps0 = 0.f, ps1 = 0.f;
        #pragma unroll
        for (int nt = 0; nt < 8; ++nt) {
            s[nt][0] = __expf(s[nt][0] - mn0);
            s[nt][1] = __expf(s[nt][1] - mn0);
            s[nt][2] = __expf(s[nt][2] - mn1);
            s[nt][3] = __expf(s[nt][3] - mn1);
            ps0 += s[nt][0] + s[nt][1];
            ps1 += s[nt][2] + s[nt][3];
        }
        ps0 += __shfl_xor_sync(0xffffffffu, ps0, 1);
        ps0 += __shfl_xor_sync(0xffffffffu, ps0, 2);
        ps1 += __shfl_xor_sync(0xffffffffu, ps1, 1);
        ps1 += __shfl_xor_sync(0xffffffffu, ps1, 2);
        l0 = l0 * c0 + ps0;
        l1 = l1 * c1 + ps1;

        #pragma unroll
        for (int nt = 0; nt < 8; ++nt) {
            o[nt][0] *= c0; o[nt][1] *= c0;
            o[nt][2] *= c1; o[nt][3] *= c1;
        }

        const int l1i = (lane & ~3) | (tig >> 1);
        const int l2i = (lane & ~3) | ((tig >> 1) + 2);
        const bool odd = (tig & 1);
        #pragma unroll
        for (int jt = 0; jt < 8; ++jt) {
            float e0 = __shfl_sync(0xffffffffu, s[jt][0], l1i);
            float q0 = __shfl_sync(0xffffffffu, s[jt][1], l1i);
            float e1 = __shfl_sync(0xffffffffu, s[jt][2], l1i);
            float q1 = __shfl_sync(0xffffffffu, s[jt][3], l1i);
            float e2 = __shfl_sync(0xffffffffu, s[jt][0], l2i);
            float q2 = __shfl_sync(0xffffffffu, s[jt][1], l2i);
            float e3 = __shfl_sync(0xffffffffu, s[jt][2], l2i);
            float q3 = __shfl_sync(0xffffffffu, s[jt][3], l2i);
            uint32_t a[4];
            a[0] = f2tf(odd ? q0 : e0);
            a[1] = f2tf(odd ? q1 : e1);
            a[2] = f2tf(odd ? q2 : e2);
            a[3] = f2tf(odd ? q3 : e3);
            #pragma unroll
            for (int nt = 0; nt < 8; ++nt) {
                const int vb = (nt * 8 + g) * AV_LD + jt * 8 + tig;
                mma_tf32(o[nt], a, Vt[vb], Vt[vb + 4]);
            }
        }
    }

    const float i0f = 1.0f / l0;
    const float i1f = 1.0f / l1;
    const int r0 = i0 + qrow + g;
    const int r1 = r0 + 8;
    #pragma unroll
    for (int nt = 0; nt < 8; ++nt) {
        const int col = hoff + nt * 8 + 2 * tig;
        *(float2*)(Og + (size_t)r0 * HDIM + col) =
            make_float2(o[nt][0] * i0f, o[nt][1] * i0f);
        *(float2*)(Og + (size_t)r1 * HDIM + col) =
            make_float2(o[nt][2] * i1f, o[nt][3] * i1f);
    }
}

// ---------------------------------------------------------------------------
// SwiGLU elementwise
// ---------------------------------------------------------------------------
__global__ void __launch_bounds__(256) silu_mul_kernel(
    const float* __restrict__ g, const float* __restrict__ u,
    float* __restrict__ out, int n4)
{
    const int i = blockIdx.x * blockDim.x + threadIdx.x;
    if (i >= n4) return;
    float4 gv = ((const float4*)g)[i];
    float4 uv = ((const float4*)u)[i];
    float4 o;
    o.x = gv.x * (1.0f / (1.0f + __expf(-gv.x))) * uv.x;
    o.y = gv.y * (1.0f / (1.0f + __expf(-gv.y))) * uv.y;
    o.z = gv.z * (1.0f / (1.0f + __expf(-gv.z))) * uv.z;
    o.w = gv.w * (1.0f / (1.0f + __expf(-gv.w))) * uv.w;
    ((float4*)out)[i] = o;
}

// ---------------------------------------------------------------------------
// Launch sequence
// ---------------------------------------------------------------------------
extern "C" void kernel_launch(void* const* d_in, const int* in_sizes, int n_in,
                              void* d_out, int out_size)
{
    (void)in_sizes; (void)n_in; (void)out_size;

    const float* hidden   = (const float*)d_in[0];
    const float* context  = (const float*)d_in[1];
    const float* sa_norm  = (const float*)d_in[2];
    const float* sa_wq    = (const float*)d_in[3];
    const float* sa_wk    = (const float*)d_in[4];
    const float* sa_wv    = (const float*)d_in[5];
    const float* sa_wo    = (const float*)d_in[6];
    const float* ca_norm  = (const float*)d_in[7];
    const float* ca_wq    = (const float*)d_in[8];
    const float* ca_wk    = (const float*)d_in[9];
    const float* ca_wv    = (const float*)d_in[10];
    const float* ca_wo    = (const float*)d_in[11];
    const float* mlp_norm = (const float*)d_in[12];
    const float* w_gate   = (const float*)d_in[13];
    const float* w_up     = (const float*)d_in[14];
    const float* w_down   = (const float*)d_in[15];
    float* out = (float*)d_out;

    float *xn, *q, *k, *v, *att, *h1, *h2, *gate, *up, *gu;
    cudaGetSymbolAddress((void**)&xn,   g_xn);
    cudaGetSymbolAddress((void**)&q,    g_q);
    cudaGetSymbolAddress((void**)&k,    g_k);
    cudaGetSymbolAddress((void**)&v,    g_v);
    cudaGetSymbolAddress((void**)&att,  g_att);
    cudaGetSymbolAddress((void**)&h1,   g_h1);
    cudaGetSymbolAddress((void**)&h2,   g_h2);
    cudaGetSymbolAddress((void**)&gate, g_gate);
    cudaGetSymbolAddress((void**)&up,   g_up);
    cudaGetSymbolAddress((void**)&gu,   g_gu);

    cudaFuncSetAttribute(attn_tc_kernel,
                         cudaFuncAttributeMaxDynamicSharedMemorySize, ATT_SMEM);
    cudaFuncSetAttribute(gemm_tf32_kernel,
                         cudaFuncAttributeMaxDynamicSharedMemorySize, GEMM_SMEM);

    const dim3 blk(256);
    const dim3 gQKV(HDIM / 64, SQ / 128, 3);   // 768 CTAs
    const dim3 gKV (HDIM / 64, SQ / 128, 2);   // 512
    const dim3 gO  (HDIM / 64, SQ / 128, 1);   // 256
    const dim3 gGU (ISZ  / 64, SQ / 128, 2);   // 2048
    const dim3 gatt(SQ / 128, NH);             // 256

    // ---- Self-attention ----
    rmsnorm_kernel<<<SQ, blk>>>(hidden, sa_norm, xn);
    gemm_tf32_kernel<<<gQKV, blk, GEMM_SMEM>>>(xn, sa_wq, sa_wk, sa_wv, nullptr,
                                               q, k, v, SQ, HDIM, HDIM);
    attn_tc_kernel<<<gatt, blk, ATT_SMEM>>>(q, k, v, att);
    gemm_tf32_kernel<<<gO, blk, GEMM_SMEM>>>(att, sa_wo, sa_wo, sa_wo, hidden,
                                             h1, h1, h1, SQ, HDIM, HDIM);

    // ---- Cross-attention ----
    rmsnorm_kernel<<<SQ, blk>>>(h1, ca_norm, xn);
    gemm_tf32_kernel<<<gO, blk, GEMM_SMEM>>>(xn, ca_wq, ca_wq, ca_wq, nullptr,
                                             q, q, q, SQ, HDIM, HDIM);
    gemm_tf32_kernel<<<gKV, blk, GEMM_SMEM>>>(context, ca_wk, ca_wv, ca_wv,
                                              nullptr, k, v, v, SQ, HDIM, HDIM);
    attn_tc_kernel<<<gatt, blk, ATT_SMEM>>>(q, k, v, att);
    gemm_tf32_kernel<<<gO, blk, GEMM_SMEM>>>(att, ca_wo, ca_wo, ca_wo, h1,
                                             h2, h2, h2, SQ, HDIM, HDIM);

    // ---- MLP ----
    rmsnorm_kernel<<<SQ, blk>>>(h2, mlp_norm, xn);
    gemm_tf32_kernel<<<gGU, blk, GEMM_SMEM>>>(xn, w_gate, w_up, w_up, nullptr,
                                              gate, up, up, SQ, ISZ, HDIM);
    silu_mul_kernel<<<(SQ * ISZ / 4 + 255) / 256, blk>>>(gate, up, gu,
                                                         SQ * ISZ / 4);
    gemm_tf32_kernel<<<gO, blk, GEMM_SMEM>>>(gu, w_down, w_down, w_down, h2,
                                             out, out, out, SQ, HDIM, ISZ);
}

// round 9
// speedup vs baseline: 1.0894x; 1.0894x over previous
#include <cuda_runtime.h>
#include <math.h>
#include <stdint.h>

// ---------------------------------------------------------------------------
// Problem dimensions
// ---------------------------------------------------------------------------
#define SQ   2048
#define HDIM 1024
#define NH   16
#define HD   64
#define ISZ  4096

// ---------------------------------------------------------------------------
// Scratch
// ---------------------------------------------------------------------------
__device__ float g_xn [SQ * HDIM];
__device__ float g_q  [SQ * HDIM];
__device__ float g_k  [SQ * HDIM];
__device__ float g_v  [SQ * HDIM];
__device__ float g_att[SQ * HDIM];
__device__ float g_h1 [SQ * HDIM];
__device__ float g_h2 [SQ * HDIM];
__device__ float g_gate[SQ * ISZ];
__device__ float g_up  [SQ * ISZ];
__device__ float g_gu  [SQ * ISZ];

// ---------------------------------------------------------------------------
// Helpers
// ---------------------------------------------------------------------------
__device__ __forceinline__ uint32_t f2tf(float f) {
    uint32_t r;
    asm("cvt.rna.tf32.f32 %0, %1;" : "=r"(r) : "f"(f));
    return r;
}

__device__ __forceinline__ void mma_tf32(float* c, const uint32_t* a,
                                         uint32_t b0, uint32_t b1) {
    asm volatile(
        "mma.sync.aligned.m16n8k8.row.col.f32.tf32.tf32.f32 "
        "{%0,%1,%2,%3}, {%4,%5,%6,%7}, {%8,%9}, {%0,%1,%2,%3};"
        : "+f"(c[0]), "+f"(c[1]), "+f"(c[2]), "+f"(c[3])
        : "r"(a[0]), "r"(a[1]), "r"(a[2]), "r"(a[3]), "r"(b0), "r"(b1));
}

__device__ __forceinline__ void cp16(uint32_t smem_dst, const void* gsrc) {
    asm volatile("cp.async.ca.shared.global [%0], [%1], 16;\n"
                 :: "r"(smem_dst), "l"(gsrc));
}
__device__ __forceinline__ void cp_commit() {
    asm volatile("cp.async.commit_group;\n" ::: "memory");
}
template <int N>
__device__ __forceinline__ void cp_wait() {
    asm volatile("cp.async.wait_group %0;\n" :: "n"(N) : "memory");
}

// ---------------------------------------------------------------------------
// RMSNorm
// ---------------------------------------------------------------------------
__global__ void __launch_bounds__(256) rmsnorm_kernel(
    const float* __restrict__ x, const float* __restrict__ w,
    float* __restrict__ y)
{
    const int row = blockIdx.x;
    const int t   = threadIdx.x;
    float4 vx = ((const float4*)(x + (size_t)row * HDIM))[t];
    float s = vx.x*vx.x + vx.y*vx.y + vx.z*vx.z + vx.w*vx.w;
    #pragma unroll
    for (int o = 16; o; o >>= 1) s += __shfl_xor_sync(0xffffffffu, s, o);

    __shared__ float red[8];
    __shared__ float s_inv;
    if ((t & 31) == 0) red[t >> 5] = s;
    __syncthreads();
    if (t == 0) {
        float tot = 0.f;
        #pragma unroll
        for (int i = 0; i < 8; ++i) tot += red[i];
        s_inv = 1.0f / sqrtf(tot * (1.0f / (float)HDIM) + 1e-6f);
    }
    __syncthreads();
    const float r = s_inv;
    float4 vw = ((const float4*)w)[t];
    float4 o4 = make_float4(vx.x*r*vw.x, vx.y*r*vw.y, vx.z*r*vw.z, vx.w*r*vw.w);
    ((float4*)(y + (size_t)row * HDIM))[t] = o4;
}

// ---------------------------------------------------------------------------
// tf32 mma.sync GEMM, 3-stage cp.async pipeline, register-held fragments.
// C[M,N] = A[M,K] @ B[K,N] (+R), row-major. BM=128, BN=64, BK=32.
// 8 warps (4m x 2n), warp tile 32x32. blockIdx.z: fused siblings.
// __launch_bounds__(256, 1): let ptxas keep the whole K-tile fragment file
// (96 words) in registers so all 64 LDS issue before the 32 MMAs.
// GB_LD = 72: B fragment loads conflict-free ((tig*8+g)%32 all distinct).
// ---------------------------------------------------------------------------
#define GA_LD 36                 // A row stride: (g*4+tig)%32 distinct
#define GB_LD 72                 // B row stride: (tig*8+g)%32 distinct
#define A_STG (128 * GA_LD)
#define B_STG (32 * GB_LD)
#define GEMM_SMEM ((3 * A_STG + 3 * B_STG) * 4)

__global__ void __launch_bounds__(256, 1) gemm_tf32_kernel(
    const float* __restrict__ A,
    const float* __restrict__ B0, const float* __restrict__ B1,
    const float* __restrict__ B2,
    const float* __restrict__ R,
    float* __restrict__ C0, float* __restrict__ C1, float* __restrict__ C2,
    int M, int N, int K)
{
    extern __shared__ uint32_t smw[];
    uint32_t* As = smw;              // [3][A_STG]
    uint32_t* Bs = smw + 3 * A_STG;  // [3][B_STG]

    const float* B = (blockIdx.z == 0) ? B0 : (blockIdx.z == 1 ? B1 : B2);
    float*       C = (blockIdx.z == 0) ? C0 : (blockIdx.z == 1 ? C1 : C2);

    const int tid  = threadIdx.x;
    const int lane = tid & 31;
    const int wid  = tid >> 5;
    const int g    = lane >> 2;
    const int tig  = lane & 3;
    const int wm   = (wid >> 1) * 32;
    const int wn   = (wid & 1) * 32;
    const int bm   = blockIdx.y * 128;
    const int bn   = blockIdx.x * 64;

    float acc[2][4][4];
    #pragma unroll
    for (int mt = 0; mt < 2; ++mt)
        #pragma unroll
        for (int nt = 0; nt < 4; ++nt)
            #pragma unroll
            for (int e = 0; e < 4; ++e) acc[mt][nt][e] = 0.f;

    const int niter = K >> 5;   // BK = 32

    auto issue = [&](int i, int s) {
        const int k0 = i << 5;
        #pragma unroll
        for (int it = 0; it < 4; ++it) {
            const int chunk = tid + it * 256;
            const int r = chunk >> 3;
            const int j = (chunk & 7) << 2;
            uint32_t dst = (uint32_t)__cvta_generic_to_shared(
                &As[s * A_STG + r * GA_LD + j]);
            cp16(dst, A + (size_t)(bm + r) * K + k0 + j);
        }
        #pragma unroll
        for (int it = 0; it < 2; ++it) {
            const int chunk = tid + it * 256;
            const int r = chunk >> 4;
            const int c = (chunk & 15) << 2;
            uint32_t dst = (uint32_t)__cvta_generic_to_shared(
                &Bs[s * B_STG + r * GB_LD + c]);
            cp16(dst, B + (size_t)(k0 + r) * N + bn + c);
        }
    };

    issue(0, 0);
    cp_commit();                     // G0 = tile 0
    if (niter > 1) issue(1, 1);
    cp_commit();                     // G1 = tile 1 (or empty)

    for (int i = 0; i < niter; ++i) {
        const int s = i - (i / 3) * 3;          // i % 3
        cp_wait<1>();                            // tile i resident
        __syncthreads();

        // ---- All 96 fragment words for this K-tile into registers ----
        uint32_t bf[4][4][2];
        uint32_t af[4][2][4];
        const uint32_t* Bst = Bs + s * B_STG;
        const uint32_t* Ast = As + s * A_STG;
        #pragma unroll
        for (int kt = 0; kt < 4; ++kt) {
            #pragma unroll
            for (int nt = 0; nt < 4; ++nt) {
                const int n = wn + nt * 8 + g;
                bf[kt][nt][0] = Bst[(kt * 8 + tig)     * GB_LD + n];
                bf[kt][nt][1] = Bst[(kt * 8 + tig + 4) * GB_LD + n];
            }
            #pragma unroll
            for (int mt = 0; mt < 2; ++mt) {
                const int base = (wm + mt * 16 + g) * GA_LD + kt * 8 + tig;
                af[kt][mt][0] = Ast[base];
                af[kt][mt][1] = Ast[base + 8 * GA_LD];
                af[kt][mt][2] = Ast[base + 4];
                af[kt][mt][3] = Ast[base + 8 * GA_LD + 4];
            }
        }

        // ---- 32 MMAs, 8 independent accumulator chains ----
        #pragma unroll
        for (int kt = 0; kt < 4; ++kt)
            #pragma unroll
            for (int mt = 0; mt < 2; ++mt)
                #pragma unroll
                for (int nt = 0; nt < 4; ++nt)
                    mma_tf32(acc[mt][nt], af[kt][mt],
                             bf[kt][nt][0], bf[kt][nt][1]);

        __syncthreads();
        const int j = i + 2;
        if (j < niter) issue(j, j - (j / 3) * 3);
        cp_commit();       // UNCONDITIONAL: keeps group accounting aligned
    }

    // Epilogue
    #pragma unroll
    for (int mt = 0; mt < 2; ++mt) {
        const int r0 = bm + wm + mt * 16 + g;
        const int r1 = r0 + 8;
        #pragma unroll
        for (int nt = 0; nt < 4; ++nt) {
            const int col = bn + wn + nt * 8 + 2 * tig;
            float2 v0 = make_float2(acc[mt][nt][0], acc[mt][nt][1]);
            float2 v1 = make_float2(acc[mt][nt][2], acc[mt][nt][3]);
            if (R) {
                float2 a0 = *(const float2*)(R + (size_t)r0 * N + col);
                float2 a1 = *(const float2*)(R + (size_t)r1 * N + col);
                v0.x += a0.x; v0.y += a0.y;
                v1.x += a1.x; v1.y += a1.y;
            }
            *(float2*)(C + (size_t)r0 * N + col) = v0;
            *(float2*)(C + (size_t)r1 * N + col) = v1;
        }
    }
}

// ---------------------------------------------------------------------------
// Flash attention with tf32 mma.sync (proven correct, unchanged)
// ---------------------------------------------------------------------------
#define AQ_LD 68
#define AV_LD 67
#define ATT_SMEM ((128 * AQ_LD + 64 * AQ_LD + 64 * AV_LD) * 4)

__global__ void __launch_bounds__(256) attn_tc_kernel(
    const float* __restrict__ Qg, const float* __restrict__ Kg,
    const float* __restrict__ Vg, float* __restrict__ Og)
{
    extern __shared__ uint32_t sm[];
    uint32_t* Qs = sm;
    uint32_t* Ks = sm + 128 * AQ_LD;
    uint32_t* Vt = sm + 128 * AQ_LD + 64 * AQ_LD;

    const int tid  = threadIdx.x;
    const int lane = tid & 31;
    const int wid  = tid >> 5;
    const int g    = lane >> 2;
    const int tig  = lane & 3;
    const int i0   = blockIdx.x * 128;
    const int hoff = blockIdx.y * HD;
    const int qrow = wid * 16;

    {
        const float scale = 0.125f;
        #pragma unroll
        for (int it = 0; it < 8; ++it) {
            const int r  = it * 16 + (tid >> 4);
            const int c4 = (tid & 15) << 2;
            float4 v = *(const float4*)(Qg + (size_t)(i0 + r) * HDIM + hoff + c4);
            Qs[r * AQ_LD + c4 + 0] = f2tf(v.x * scale);
            Qs[r * AQ_LD + c4 + 1] = f2tf(v.y * scale);
            Qs[r * AQ_LD + c4 + 2] = f2tf(v.z * scale);
            Qs[r * AQ_LD + c4 + 3] = f2tf(v.w * scale);
        }
    }

    float m0 = -1e30f, m1 = -1e30f;
    float l0 = 0.f, l1 = 0.f;
    float o[8][4];
    #pragma unroll
    for (int nt = 0; nt < 8; ++nt)
        #pragma unroll
        for (int e = 0; e < 4; ++e) o[nt][e] = 0.f;

    for (int j0 = 0; j0 < SQ; j0 += 64) {
        __syncthreads();
        #pragma unroll
        for (int it = 0; it < 4; ++it) {
            const int r  = it * 16 + (tid >> 4);
            const int c4 = (tid & 15) << 2;
            float4 kv = *(const float4*)(Kg + (size_t)(j0 + r) * HDIM + hoff + c4);
            Ks[r * AQ_LD + c4 + 0] = f2tf(kv.x);
            Ks[r * AQ_LD + c4 + 1] = f2tf(kv.y);
            Ks[r * AQ_LD + c4 + 2] = f2tf(kv.z);
            Ks[r * AQ_LD + c4 + 3] = f2tf(kv.w);
            float4 vv = *(const float4*)(Vg + (size_t)(j0 + r) * HDIM + hoff + c4);
            Vt[(c4 + 0) * AV_LD + r] = f2tf(vv.x);
            Vt[(c4 + 1) * AV_LD + r] = f2tf(vv.y);
            Vt[(c4 + 2) * AV_LD + r] = f2tf(vv.z);
            Vt[(c4 + 3) * AV_LD + r] = f2tf(vv.w);
        }
        __syncthreads();

        float s[8][4];
        #pragma unroll
        for (int nt = 0; nt < 8; ++nt)
            #pragma unroll
            for (int e = 0; e < 4; ++e) s[nt][e] = 0.f;

        #pragma unroll
        for (int kt = 0; kt < 8; ++kt) {
            uint32_t a[4];
            const int base = (qrow + g) * AQ_LD + kt * 8 + tig;
            a[0] = Qs[base];
            a[1] = Qs[base + 8 * AQ_LD];
            a[2] = Qs[base + 4];
            a[3] = Qs[base + 8 * AQ_LD + 4];
            #pragma unroll
            for (int nt = 0; nt < 8; ++nt) {
                const int jb = (nt * 8 + g) * AQ_LD + kt * 8 + tig;
                mma_tf32(s[nt], a, Ks[jb], Ks[jb + 4]);
            }
        }

        float mt0 = -1e30f, mt1 = -1e30f;
        #pragma unroll
        for (int nt = 0; nt < 8; ++nt) {
            mt0 = fmaxf(mt0, fmaxf(s[nt][0], s[nt][1]));
            mt1 = fmaxf(mt1, fmaxf(s[nt][2], s[nt][3]));
        }
        mt0 = fmaxf(mt0, __shfl_xor_sync(0xffffffffu, mt0, 1));
        mt0 = fmaxf(mt0, __shfl_xor_sync(0xffffffffu, mt0, 2));
        mt1 = fmaxf(mt1, __shfl_xor_sync(0xffffffffu, mt1, 1));
        mt1 = fmaxf(mt1, __shfl_xor_sync(0xffffffffu, mt1, 2));

        const float mn0 = fmaxf(m0, mt0);
        const float mn1 = fmaxf(m1, mt1);
        const float c0 = __expf(m0 - mn0);
        const float c1 = __expf(m1 - mn1);
        m0 = mn0; m1 = mn1;

        float ps0 = 0.f, ps1 = 0.f;
        #pragma unroll
        for (int nt = 0; nt < 8; ++nt) {
            s[nt][0] = __expf(s[nt][0] - mn0);
            s[nt][1] = __expf(s[nt][1] - mn0);
            s[nt][2] = __expf(s[nt][2] - mn1);
            s[nt][3] = __expf(s[nt][3] - mn1);
            ps0 += s[nt][0] + s[nt][1];
            ps1 += s[nt][2] + s[nt][3];
        }
        ps0 += __shfl_xor_sync(0xffffffffu, ps0, 1);
        ps0 += __shfl_xor_sync(0xffffffffu, ps0, 2);
        ps1 += __shfl_xor_sync(0xffffffffu, ps1, 1);
        ps1 += __shfl_xor_sync(0xffffffffu, ps1, 2);
        l0 = l0 * c0 + ps0;
        l1 = l1 * c1 + ps1;

        #pragma unroll
        for (int nt = 0; nt < 8; ++nt) {
            o[nt][0] *= c0; o[nt][1] *= c0;
            o[nt][2] *= c1; o[nt][3] *= c1;
        }

        const int l1i = (lane & ~3) | (tig >> 1);
        const int l2i = (lane & ~3) | ((tig >> 1) + 2);
        const bool odd = (tig & 1);
        #pragma unroll
        for (int jt = 0; jt < 8; ++jt) {
            float e0 = __shfl_sync(0xffffffffu, s[jt][0], l1i);
            float q0 = __shfl_sync(0xffffffffu, s[jt][1], l1i);
            float e1 = __shfl_sync(0xffffffffu, s[jt][2], l1i);
            float q1 = __shfl_sync(0xffffffffu, s[jt][3], l1i);
            float e2 = __shfl_sync(0xffffffffu, s[jt][0], l2i);
            float q2 = __shfl_sync(0xffffffffu, s[jt][1], l2i);
            float e3 = __shfl_sync(0xffffffffu, s[jt][2], l2i);
            float q3 = __shfl_sync(0xffffffffu, s[jt][3], l2i);
            uint32_t a[4];
            a[0] = f2tf(odd ? q0 : e0);
            a[1] = f2tf(odd ? q1 : e1);
            a[2] = f2tf(odd ? q2 : e2);
            a[3] = f2tf(odd ? q3 : e3);
            #pragma unroll
            for (int nt = 0; nt < 8; ++nt) {
                const int vb = (nt * 8 + g) * AV_LD + jt * 8 + tig;
                mma_tf32(o[nt], a, Vt[vb], Vt[vb + 4]);
            }
        }
    }

    const float i0f = 1.0f / l0;
    const float i1f = 1.0f / l1;
    const int r0 = i0 + qrow + g;
    const int r1 = r0 + 8;
    #pragma unroll
    for (int nt = 0; nt < 8; ++nt) {
        const int col = hoff + nt * 8 + 2 * tig;
        *(float2*)(Og + (size_t)r0 * HDIM + col) =
            make_float2(o[nt][0] * i0f, o[nt][1] * i0f);
        *(float2*)(Og + (size_t)r1 * HDIM + col) =
            make_float2(o[nt][2] * i1f, o[nt][3] * i1f);
    }
}

// ---------------------------------------------------------------------------
// SwiGLU elementwise
// ---------------------------------------------------------------------------
__global__ void __launch_bounds__(256) silu_mul_kernel(
    const float* __restrict__ g, const float* __restrict__ u,
    float* __restrict__ out, int n4)
{
    const int i = blockIdx.x * blockDim.x + threadIdx.x;
    if (i >= n4) return;
    float4 gv = ((const float4*)g)[i];
    float4 uv = ((const float4*)u)[i];
    float4 o;
    o.x = gv.x * (1.0f / (1.0f + __expf(-gv.x))) * uv.x;
    o.y = gv.y * (1.0f / (1.0f + __expf(-gv.y))) * uv.y;
    o.z = gv.z * (1.0f / (1.0f + __expf(-gv.z))) * uv.z;
    o.w = gv.w * (1.0f / (1.0f + __expf(-gv.w))) * uv.w;
    ((float4*)out)[i] = o;
}

// ---------------------------------------------------------------------------
// Launch sequence
// ---------------------------------------------------------------------------
extern "C" void kernel_launch(void* const* d_in, const int* in_sizes, int n_in,
                              void* d_out, int out_size)
{
    (void)in_sizes; (void)n_in; (void)out_size;

    const float* hidden   = (const float*)d_in[0];
    const float* context  = (const float*)d_in[1];
    const float* sa_norm  = (const float*)d_in[2];
    const float* sa_wq    = (const float*)d_in[3];
    const float* sa_wk    = (const float*)d_in[4];
    const float* sa_wv    = (const float*)d_in[5];
    const float* sa_wo    = (const float*)d_in[6];
    const float* ca_norm  = (const float*)d_in[7];
    const float* ca_wq    = (const float*)d_in[8];
    const float* ca_wk    = (const float*)d_in[9];
    const float* ca_wv    = (const float*)d_in[10];
    const float* ca_wo    = (const float*)d_in[11];
    const float* mlp_norm = (const float*)d_in[12];
    const float* w_gate   = (const float*)d_in[13];
    const float* w_up     = (const float*)d_in[14];
    const float* w_down   = (const float*)d_in[15];
    float* out = (float*)d_out;

    float *xn, *q, *k, *v, *att, *h1, *h2, *gate, *up, *gu;
    cudaGetSymbolAddress((void**)&xn,   g_xn);
    cudaGetSymbolAddress((void**)&q,    g_q);
    cudaGetSymbolAddress((void**)&k,    g_k);
    cudaGetSymbolAddress((void**)&v,    g_v);
    cudaGetSymbolAddress((void**)&att,  g_att);
    cudaGetSymbolAddress((void**)&h1,   g_h1);
    cudaGetSymbolAddress((void**)&h2,   g_h2);
    cudaGetSymbolAddress((void**)&gate, g_gate);
    cudaGetSymbolAddress((void**)&up,   g_up);
    cudaGetSymbolAddress((void**)&gu,   g_gu);

    cudaFuncSetAttribute(attn_tc_kernel,
                         cudaFuncAttributeMaxDynamicSharedMemorySize, ATT_SMEM);
    cudaFuncSetAttribute(gemm_tf32_kernel,
                         cudaFuncAttributeMaxDynamicSharedMemorySize, GEMM_SMEM);

    const dim3 blk(256);
    const dim3 gQKV(HDIM / 64, SQ / 128, 3);   // 768 CTAs
    const dim3 gKV (HDIM / 64, SQ / 128, 2);   // 512
    const dim3 gO  (HDIM / 64, SQ / 128, 1);   // 256
    const dim3 gGU (ISZ  / 64, SQ / 128, 2);   // 2048
    const dim3 gatt(SQ / 128, NH);             // 256

    // ---- Self-attention ----
    rmsnorm_kernel<<<SQ, blk>>>(hidden, sa_norm, xn);
    gemm_tf32_kernel<<<gQKV, blk, GEMM_SMEM>>>(xn, sa_wq, sa_wk, sa_wv, nullptr,
                                               q, k, v, SQ, HDIM, HDIM);
    attn_tc_kernel<<<gatt, blk, ATT_SMEM>>>(q, k, v, att);
    gemm_tf32_kernel<<<gO, blk, GEMM_SMEM>>>(att, sa_wo, sa_wo, sa_wo, hidden,
                                             h1, h1, h1, SQ, HDIM, HDIM);

    // ---- Cross-attention ----
    rmsnorm_kernel<<<SQ, blk>>>(h1, ca_norm, xn);
    gemm_tf32_kernel<<<gO, blk, GEMM_SMEM>>>(xn, ca_wq, ca_wq, ca_wq, nullptr,
                                             q, q, q, SQ, HDIM, HDIM);
    gemm_tf32_kernel<<<gKV, blk, GEMM_SMEM>>>(context, ca_wk, ca_wv, ca_wv,
                                              nullptr, k, v, v, SQ, HDIM, HDIM);
    attn_tc_kernel<<<gatt, blk, ATT_SMEM>>>(q, k, v, att);
    gemm_tf32_kernel<<<gO, blk, GEMM_SMEM>>>(att, ca_wo, ca_wo, ca_wo, h1,
                                             h2, h2, h2, SQ, HDIM, HDIM);

    // ---- MLP ----
    rmsnorm_kernel<<<SQ, blk>>>(h2, mlp_norm, xn);
    gemm_tf32_kernel<<<gGU, blk, GEMM_SMEM>>>(xn, w_gate, w_up, w_up, nullptr,
                                              gate, up, up, SQ, ISZ, HDIM);
    silu_mul_kernel<<<(SQ * ISZ / 4 + 255) / 256, blk>>>(gate, up, gu,
                                                         SQ * ISZ / 4);
    gemm_tf32_kernel<<<gO, blk, GEMM_SMEM>>>(gu, w_down, w_down, w_down, h2,
                                             out, out, out, SQ, HDIM, ISZ);
}

// round 12
// speedup vs baseline: 1.3606x; 1.2489x over previous
#include <cuda_runtime.h>
#include <cuda_fp16.h>
#include <math.h>
#include <stdint.h>

// ---------------------------------------------------------------------------
// Problem dimensions
// ---------------------------------------------------------------------------
#define SQ   2048
#define HDIM 1024
#define NH   16
#define HD   64
#define ISZ  4096

// ---------------------------------------------------------------------------
// Scratch
// ---------------------------------------------------------------------------
__device__ __half g_xn [SQ * HDIM];
__device__ __half g_q  [SQ * HDIM];
__device__ __half g_k  [SQ * HDIM];
__device__ __half g_v  [SQ * HDIM];
__device__ __half g_att[SQ * HDIM];
__device__ __half g_ctx[SQ * HDIM];
__device__ float  g_h1 [SQ * HDIM];
__device__ float  g_h2 [SQ * HDIM];
__device__ __half g_gate[SQ * ISZ];
__device__ __half g_up  [SQ * ISZ];
__device__ __half g_gu  [SQ * ISZ];
// transposed fp16 weights [N][K]
__device__ __half g_wt_saq[HDIM * HDIM];
__device__ __half g_wt_sak[HDIM * HDIM];
__device__ __half g_wt_sav[HDIM * HDIM];
__device__ __half g_wt_sao[HDIM * HDIM];
__device__ __half g_wt_caq[HDIM * HDIM];
__device__ __half g_wt_cak[HDIM * HDIM];
__device__ __half g_wt_cav[HDIM * HDIM];
__device__ __half g_wt_cao[HDIM * HDIM];
__device__ __half g_wt_g  [ISZ * HDIM];
__device__ __half g_wt_u  [ISZ * HDIM];
__device__ __half g_wt_d  [HDIM * ISZ];

// ---------------------------------------------------------------------------
// Helpers
// ---------------------------------------------------------------------------
__device__ __forceinline__ uint32_t f2tf(float f) {
    uint32_t r;
    asm("cvt.rna.tf32.f32 %0, %1;" : "=r"(r) : "f"(f));
    return r;
}

__device__ __forceinline__ void mma_tf32(float* c, const uint32_t* a,
                                         uint32_t b0, uint32_t b1) {
    asm volatile(
        "mma.sync.aligned.m16n8k8.row.col.f32.tf32.tf32.f32 "
        "{%0,%1,%2,%3}, {%4,%5,%6,%7}, {%8,%9}, {%0,%1,%2,%3};"
        : "+f"(c[0]), "+f"(c[1]), "+f"(c[2]), "+f"(c[3])
        : "r"(a[0]), "r"(a[1]), "r"(a[2]), "r"(a[3]), "r"(b0), "r"(b1));
}

// fp16 MMA: D(f32) += A(f16,row) * B(f16,col); 16x8x16
__device__ __forceinline__ void mma_f16(float* c, const uint32_t* a,
                                        uint32_t b0, uint32_t b1) {
    asm volatile(
        "mma.sync.aligned.m16n8k16.row.col.f32.f16.f16.f32 "
        "{%0,%1,%2,%3}, {%4,%5,%6,%7}, {%8,%9}, {%0,%1,%2,%3};"
        : "+f"(c[0]), "+f"(c[1]), "+f"(c[2]), "+f"(c[3])
        : "r"(a[0]), "r"(a[1]), "r"(a[2]), "r"(a[3]), "r"(b0), "r"(b1));
}

__device__ __forceinline__ void cp16(uint32_t smem_dst, const void* gsrc) {
    asm volatile("cp.async.ca.shared.global [%0], [%1], 16;\n"
                 :: "r"(smem_dst), "l"(gsrc));
}
__device__ __forceinline__ void cp_commit() {
    asm volatile("cp.async.commit_group;\n" ::: "memory");
}
template <int N>
__device__ __forceinline__ void cp_wait() {
    asm volatile("cp.async.wait_group %0;\n" :: "n"(N) : "memory");
}

// ---------------------------------------------------------------------------
// Weight transpose + fp32->fp16: out[n*K+k] = (half)in[k*N+n]
// ---------------------------------------------------------------------------
__global__ void __launch_bounds__(256) tr16_kernel(
    const float* __restrict__ in, __half* __restrict__ out, int K, int N)
{
    __shared__ float t[32][33];
    const int tx = threadIdx.x & 31;
    const int ty = threadIdx.x >> 5;
    const int n0 = blockIdx.x * 32;
    const int k0 = blockIdx.y * 32;
    #pragma unroll
    for (int j = 0; j < 4; ++j)
        t[ty + j * 8][tx] = in[(size_t)(k0 + ty + j * 8) * N + n0 + tx];
    __syncthreads();
    #pragma unroll
    for (int j = 0; j < 4; ++j)
        out[(size_t)(n0 + ty + j * 8) * K + k0 + tx] =
            __float2half_rn(t[tx][ty + j * 8]);
}

// fp32 -> fp16 elementwise (context)
__global__ void __launch_bounds__(256) cvt16_kernel(
    const float* __restrict__ in, __half* __restrict__ out, int n4)
{
    const int i = blockIdx.x * blockDim.x + threadIdx.x;
    if (i >= n4) return;
    float4 v = ((const float4*)in)[i];
    ((half2*)out)[2 * i + 0] = __floats2half2_rn(v.x, v.y);
    ((half2*)out)[2 * i + 1] = __floats2half2_rn(v.z, v.w);
}

// ---------------------------------------------------------------------------
// RMSNorm: fp32 in -> fp16 out
// ---------------------------------------------------------------------------
__global__ void __launch_bounds__(256) rmsnorm16_kernel(
    const float* __restrict__ x, const float* __restrict__ w,
    __half* __restrict__ y)
{
    const int row = blockIdx.x;
    const int t   = threadIdx.x;
    float4 vx = ((const float4*)(x + (size_t)row * HDIM))[t];
    float s = vx.x*vx.x + vx.y*vx.y + vx.z*vx.z + vx.w*vx.w;
    #pragma unroll
    for (int o = 16; o; o >>= 1) s += __shfl_xor_sync(0xffffffffu, s, o);

    __shared__ float red[8];
    __shared__ float s_inv;
    if ((t & 31) == 0) red[t >> 5] = s;
    __syncthreads();
    if (t == 0) {
        float tot = 0.f;
        #pragma unroll
        for (int i = 0; i < 8; ++i) tot += red[i];
        s_inv = 1.0f / sqrtf(tot * (1.0f / (float)HDIM) + 1e-6f);
    }
    __syncthreads();
    const float r = s_inv;
    float4 vw = ((const float4*)w)[t];
    half2* yrow = (half2*)(y + (size_t)row * HDIM);
    yrow[2 * t + 0] = __floats2half2_rn(vx.x * r * vw.x, vx.y * r * vw.y);
    yrow[2 * t + 1] = __floats2half2_rn(vx.z * r * vw.z, vx.w * r * vw.w);
}

// ---------------------------------------------------------------------------
// fp16 mma.sync GEMM (m16n8k16), 3-stage cp.async pipeline.
// C[M,N] = A[M,K] @ Bt[N,K]^T (+R), A/Bt fp16, acc fp32.
// BM=128, BN=64, BK=32. 8 warps (4m x 2n), warp tile 32x32.
// OUTF16=1: C is fp16. OUTF16=0: C fp32 with optional fp32 residual R.
// Smem: word = 2 halves (k-pair). Row stride RS=20 words -> conflict-free
// fragment loads (g*20+tig covers all 32 banks).
// ---------------------------------------------------------------------------
#define RS16  20
#define A16_STG (128 * RS16)
#define B16_STG (64 * RS16)
#define GEMM_SMEM ((3 * A16_STG + 3 * B16_STG) * 4)

template <int OUTF16>
__global__ void __launch_bounds__(256, 2) gemm_f16_kernel(
    const __half* __restrict__ A,
    const __half* __restrict__ B0, const __half* __restrict__ B1,
    const __half* __restrict__ B2,
    const float* __restrict__ R,
    void* __restrict__ C0, void* __restrict__ C1, void* __restrict__ C2,
    int M, int N, int K)
{
    extern __shared__ uint32_t smw[];
    uint32_t* As = smw;                 // [3][A16_STG]
    uint32_t* Bs = smw + 3 * A16_STG;   // [3][B16_STG]

    const __half* B = (blockIdx.z == 0) ? B0 : (blockIdx.z == 1 ? B1 : B2);
    void*         C = (blockIdx.z == 0) ? C0 : (blockIdx.z == 1 ? C1 : C2);

    const int tid  = threadIdx.x;
    const int lane = tid & 31;
    const int wid  = tid >> 5;
    const int g    = lane >> 2;
    const int tig  = lane & 3;
    const int wm   = (wid >> 1) * 32;
    const int wn   = (wid & 1) * 32;
    const int bm   = blockIdx.y * 128;
    const int bn   = blockIdx.x * 64;

    float acc[2][4][4];
    #pragma unroll
    for (int mt = 0; mt < 2; ++mt)
        #pragma unroll
        for (int nt = 0; nt < 4; ++nt)
            #pragma unroll
            for (int e = 0; e < 4; ++e) acc[mt][nt][e] = 0.f;

    const int niter = K >> 5;   // BK = 32 halves

    auto issue = [&](int i, int s) {
        const int k0 = i << 5;
        // A tile: 128 rows x 32 halves = 512 16B-chunks / 256 thr = 2 each
        #pragma unroll
        for (int it = 0; it < 2; ++it) {
            const int chunk = tid + it * 256;
            const int r = chunk >> 2;           // 4 chunks per row
            const int c = chunk & 3;            // chunk covers 8 halves
            uint32_t dst = (uint32_t)__cvta_generic_to_shared(
                &As[s * A16_STG + r * RS16 + 4 * c]);
            cp16(dst, A + (size_t)(bm + r) * K + k0 + 8 * c);
        }
        // B tile: 64 rows x 32 halves = 256 chunks / 256 thr = 1 each
        {
            const int r = tid >> 2;
            const int c = tid & 3;
            uint32_t dst = (uint32_t)__cvta_generic_to_shared(
                &Bs[s * B16_STG + r * RS16 + 4 * c]);
            cp16(dst, B + (size_t)(bn + r) * K + k0 + 8 * c);
        }
    };

    issue(0, 0);
    cp_commit();
    if (niter > 1) issue(1, 1);
    cp_commit();

    for (int i = 0; i < niter; ++i) {
        const int s = i - (i / 3) * 3;
        cp_wait<1>();
        __syncthreads();

        const uint32_t* Ast = As + s * A16_STG;
        const uint32_t* Bst = Bs + s * B16_STG;

        // fragments for the whole K-tile (2 x k16)
        uint32_t af[2][2][4];
        uint32_t bf[2][4][2];
        #pragma unroll
        for (int kt = 0; kt < 2; ++kt) {
            #pragma unroll
            for (int nt = 0; nt < 4; ++nt) {
                const int base = (wn + nt * 8 + g) * RS16 + kt * 8 + tig;
                bf[kt][nt][0] = Bst[base];
                bf[kt][nt][1] = Bst[base + 4];
            }
            #pragma unroll
            for (int mt = 0; mt < 2; ++mt) {
                const int b0 = (wm + mt * 16 + g) * RS16 + kt * 8 + tig;
                af[kt][mt][0] = Ast[b0];
                af[kt][mt][1] = Ast[b0 + 8 * RS16];
                af[kt][mt][2] = Ast[b0 + 4];
                af[kt][mt][3] = Ast[b0 + 8 * RS16 + 4];
            }
        }

        #pragma unroll
        for (int kt = 0; kt < 2; ++kt)
            #pragma unroll
            for (int mt = 0; mt < 2; ++mt)
                #pragma unroll
                for (int nt = 0; nt < 4; ++nt)
                    mma_f16(acc[mt][nt], af[kt][mt],
                            bf[kt][nt][0], bf[kt][nt][1]);

        __syncthreads();
        const int j = i + 2;
        if (j < niter) issue(j, j - (j / 3) * 3);
        cp_commit();       // unconditional: keeps group accounting aligned
    }

    // Epilogue
    #pragma unroll
    for (int mt = 0; mt < 2; ++mt) {
        const int r0 = bm + wm + mt * 16 + g;
        const int r1 = r0 + 8;
        #pragma unroll
        for (int nt = 0; nt < 4; ++nt) {
            const int col = bn + wn + nt * 8 + 2 * tig;
            if (OUTF16) {
                __half* Ch = (__half*)C;
                *(half2*)(Ch + (size_t)r0 * N + col) =
                    __floats2half2_rn(acc[mt][nt][0], acc[mt][nt][1]);
                *(half2*)(Ch + (size_t)r1 * N + col) =
                    __floats2half2_rn(acc[mt][nt][2], acc[mt][nt][3]);
            } else {
                float* Cf = (float*)C;
                float2 v0 = make_float2(acc[mt][nt][0], acc[mt][nt][1]);
                float2 v1 = make_float2(acc[mt][nt][2], acc[mt][nt][3]);
                if (R) {
                    float2 a0 = *(const float2*)(R + (size_t)r0 * N + col);
                    float2 a1 = *(const float2*)(R + (size_t)r1 * N + col);
                    v0.x += a0.x; v0.y += a0.y;
                    v1.x += a1.x; v1.y += a1.y;
                }
                *(float2*)(Cf + (size_t)r0 * N + col) = v0;
                *(float2*)(Cf + (size_t)r1 * N + col) = v1;
            }
        }
    }
}

// ---------------------------------------------------------------------------
// Flash attention, tf32 mma core (proven). fp16 in / fp16 out.
// ---------------------------------------------------------------------------
#define AQ_LD 68
#define AV_LD 67
#define ATT_SMEM ((128 * AQ_LD + 64 * AQ_LD + 64 * AV_LD) * 4)

__global__ void __launch_bounds__(256) attn_tc_kernel(
    const __half* __restrict__ Qg, const __half* __restrict__ Kg,
    const __half* __restrict__ Vg, __half* __restrict__ Og)
{
    extern __shared__ uint32_t sm[];
    uint32_t* Qs = sm;
    uint32_t* Ks = sm + 128 * AQ_LD;
    uint32_t* Vt = sm + 128 * AQ_LD + 64 * AQ_LD;

    const int tid  = threadIdx.x;
    const int lane = tid & 31;
    const int wid  = tid >> 5;
    const int g    = lane >> 2;
    const int tig  = lane & 3;
    const int i0   = blockIdx.x * 128;
    const int hoff = blockIdx.y * HD;
    const int qrow = wid * 16;

    {
        const float scale = 0.125f;
        #pragma unroll
        for (int it = 0; it < 8; ++it) {
            const int r  = it * 16 + (tid >> 4);
            const int c4 = (tid & 15) << 2;
            const __half* p = Qg + (size_t)(i0 + r) * HDIM + hoff + c4;
            float2 f0 = __half22float2(*(const half2*)(p));
            float2 f1 = __half22float2(*(const half2*)(p + 2));
            Qs[(c4 + 0) * AQ_LD + r] = f2tf(f0.x * scale);
            Qs[(c4 + 1) * AQ_LD + r] = f2tf(f0.y * scale);
            Qs[(c4 + 2) * AQ_LD + r] = f2tf(f1.x * scale);
            Qs[(c4 + 3) * AQ_LD + r] = f2tf(f1.y * scale);
        }
    }
    // NOTE: Qs layout here is d-major like the proven kernel's K path; the
    // fragment loads below expect row-major Qs, so keep the original layout:
    // (re-store in row-major form)
    __syncthreads();
    // Rebuild Qs in row-major [row][d] (as proven kernel) from global again.
    {
        const float scale = 0.125f;
        #pragma unroll
        for (int it = 0; it < 8; ++it) {
            const int r  = it * 16 + (tid >> 4);
            const int c4 = (tid & 15) << 2;
            const __half* p = Qg + (size_t)(i0 + r) * HDIM + hoff + c4;
            float2 f0 = __half22float2(*(const half2*)(p));
            float2 f1 = __half22float2(*(const half2*)(p + 2));
            Qs[r * AQ_LD + c4 + 0] = f2tf(f0.x * scale);
            Qs[r * AQ_LD + c4 + 1] = f2tf(f0.y * scale);
            Qs[r * AQ_LD + c4 + 2] = f2tf(f1.x * scale);
            Qs[r * AQ_LD + c4 + 3] = f2tf(f1.y * scale);
        }
    }

    float m0 = -1e30f, m1 = -1e30f;
    float l0 = 0.f, l1 = 0.f;
    float o[8][4];
    #pragma unroll
    for (int nt = 0; nt < 8; ++nt)
        #pragma unroll
        for (int e = 0; e < 4; ++e) o[nt][e] = 0.f;

    for (int j0 = 0; j0 < SQ; j0 += 64) {
        __syncthreads();
        #pragma unroll
        for (int it = 0; it < 4; ++it) {
            const int r  = it * 16 + (tid >> 4);
            const int c4 = (tid & 15) << 2;
            const __half* kp = Kg + (size_t)(j0 + r) * HDIM + hoff + c4;
            float2 k0f = __half22float2(*(const half2*)(kp));
            float2 k1f = __half22float2(*(const half2*)(kp + 2));
            Ks[r * AQ_LD + c4 + 0] = f2tf(k0f.x);
            Ks[r * AQ_LD + c4 + 1] = f2tf(k0f.y);
            Ks[r * AQ_LD + c4 + 2] = f2tf(k1f.x);
            Ks[r * AQ_LD + c4 + 3] = f2tf(k1f.y);
            const __half* vp = Vg + (size_t)(j0 + r) * HDIM + hoff + c4;
            float2 v0f = __half22float2(*(const half2*)(vp));
            float2 v1f = __half22float2(*(const half2*)(vp + 2));
            Vt[(c4 + 0) * AV_LD + r] = f2tf(v0f.x);
            Vt[(c4 + 1) * AV_LD + r] = f2tf(v0f.y);
            Vt[(c4 + 2) * AV_LD + r] = f2tf(v1f.x);
            Vt[(c4 + 3) * AV_LD + r] = f2tf(v1f.y);
        }
        __syncthreads();

        float s[8][4];
        #pragma unroll
        for (int nt = 0; nt < 8; ++nt)
            #pragma unroll
            for (int e = 0; e < 4; ++e) s[nt][e] = 0.f;

        #pragma unroll
        for (int kt = 0; kt < 8; ++kt) {
            uint32_t a[4];
            const int base = (qrow + g) * AQ_LD + kt * 8 + tig;
            a[0] = Qs[base];
            a[1] = Qs[base + 8 * AQ_LD];
            a[2] = Qs[base + 4];
            a[3] = Qs[base + 8 * AQ_LD + 4];
            #pragma unroll
            for (int nt = 0; nt < 8; ++nt) {
                const int jb = (nt * 8 + g) * AQ_LD + kt * 8 + tig;
                mma_tf32(s[nt], a, Ks[jb], Ks[jb + 4]);
            }
        }

        float mt0 = -1e30f, mt1 = -1e30f;
        #pragma unroll
        for (int nt = 0; nt < 8; ++nt) {
            mt0 = fmaxf(mt0, fmaxf(s[nt][0], s[nt][1]));
            mt1 = fmaxf(mt1, fmaxf(s[nt][2], s[nt][3]));
        }
        mt0 = fmaxf(mt0, __shfl_xor_sync(0xffffffffu, mt0, 1));
        mt0 = fmaxf(mt0, __shfl_xor_sync(0xffffffffu, mt0, 2));
        mt1 = fmaxf(mt1, __shfl_xor_sync(0xffffffffu, mt1, 1));
        mt1 = fmaxf(mt1, __shfl_xor_sync(0xffffffffu, mt1, 2));

        const float mn0 = fmaxf(m0, mt0);
        const float mn1 = fmaxf(m1, mt1);
        const float c0 = __expf(m0 - mn0);
        const float c1 = __expf(m1 - mn1);
        m0 = mn0; m1 = mn1;

        float ps0 = 0.f, ps1 = 0.f;
        #pragma unroll
        for (int nt = 0; nt < 8; ++nt) {
            s[nt][0] = __expf(s[nt][0] - mn0);
            s[nt][1] = __expf(s[nt][1] - mn0);
            s[nt][2] = __expf(s[nt][2] - mn1);
            s[nt][3] = __expf(s[nt][3] - mn1);
            ps0 += s[nt][0] + s[nt][1];
            ps1 += s[nt][2] + s[nt][3];
        }
        ps0 += __shfl_xor_sync(0xffffffffu, ps0, 1);
        ps0 += __shfl_xor_sync(0xffffffffu, ps0, 2);
        ps1 += __shfl_xor_sync(0xffffffffu, ps1, 1);
        ps1 += __shfl_xor_sync(0xffffffffu, ps1, 2);
        l0 = l0 * c0 + ps0;
        l1 = l1 * c1 + ps1;

        #pragma unroll
        for (int nt = 0; nt < 8; ++nt) {
            o[nt][0] *= c0; o[nt][1] *= c0;
            o[nt][2] *= c1; o[nt][3] *= c1;
        }

        const int l1i = (lane & ~3) | (tig >> 1);
        const int l2i = (lane & ~3) | ((tig >> 1) + 2);
        const bool odd = (tig & 1);
        #pragma unroll
        for (int jt = 0; jt < 8; ++jt) {
            float e0 = __shfl_sync(0xffffffffu, s[jt][0], l1i);
            float q0 = __shfl_sync(0xffffffffu, s[jt][1], l1i);
            float e1 = __shfl_sync(0xffffffffu, s[jt][2], l1i);
            float q1 = __shfl_sync(0xffffffffu, s[jt][3], l1i);
            float e2 = __shfl_sync(0xffffffffu, s[jt][0], l2i);
            float q2 = __shfl_sync(0xffffffffu, s[jt][1], l2i);
            float e3 = __shfl_sync(0xffffffffu, s[jt][2], l2i);
            float q3 = __shfl_sync(0xffffffffu, s[jt][3], l2i);
            uint32_t a[4];
            a[0] = f2tf(odd ? q0 : e0);
            a[1] = f2tf(odd ? q1 : e1);
            a[2] = f2tf(odd ? q2 : e2);
            a[3] = f2tf(odd ? q3 : e3);
            #pragma unroll
            for (int nt = 0; nt < 8; ++nt) {
                const int vb = (nt * 8 + g) * AV_LD + jt * 8 + tig;
                mma_tf32(o[nt], a, Vt[vb], Vt[vb + 4]);
            }
        }
    }

    const float i0f = 1.0f / l0;
    const float i1f = 1.0f / l1;
    const int r0 = i0 + qrow + g;
    const int r1 = r0 + 8;
    #pragma unroll
    for (int nt = 0; nt < 8; ++nt) {
        const int col = hoff + nt * 8 + 2 * tig;
        *(half2*)(Og + (size_t)r0 * HDIM + col) =
            __floats2half2_rn(o[nt][0] * i0f, o[nt][1] * i0f);
        *(half2*)(Og + (size_t)r1 * HDIM + col) =
            __floats2half2_rn(o[nt][2] * i1f, o[nt][3] * i1f);
    }
}

// ---------------------------------------------------------------------------
// SwiGLU elementwise: fp16 in/out
// ---------------------------------------------------------------------------
__global__ void __launch_bounds__(256) silu16_kernel(
    const __half* __restrict__ g, const __half* __restrict__ u,
    __half* __restrict__ out, int n2)
{
    const int i = blockIdx.x * blockDim.x + threadIdx.x;
    if (i >= n2) return;
    float2 gf = __half22float2(((const half2*)g)[i]);
    float2 uf = __half22float2(((const half2*)u)[i]);
    float ox = gf.x * (1.0f / (1.0f + __expf(-gf.x))) * uf.x;
    float oy = gf.y * (1.0f / (1.0f + __expf(-gf.y))) * uf.y;
    ((half2*)out)[i] = __floats2half2_rn(ox, oy);
}

// ---------------------------------------------------------------------------
// Launch sequence
// ---------------------------------------------------------------------------
extern "C" void kernel_launch(void* const* d_in, const int* in_sizes, int n_in,
                              void* d_out, int out_size)
{
    (void)in_sizes; (void)n_in; (void)out_size;

    const float* hidden   = (const float*)d_in[0];
    const float* context  = (const float*)d_in[1];
    const float* sa_norm  = (const float*)d_in[2];
    const float* sa_wq    = (const float*)d_in[3];
    const float* sa_wk    = (const float*)d_in[4];
    const float* sa_wv    = (const float*)d_in[5];
    const float* sa_wo    = (const float*)d_in[6];
    const float* ca_norm  = (const float*)d_in[7];
    const float* ca_wq    = (const float*)d_in[8];
    const float* ca_wk    = (const float*)d_in[9];
    const float* ca_wv    = (const float*)d_in[10];
    const float* ca_wo    = (const float*)d_in[11];
    const float* mlp_norm = (const float*)d_in[12];
    const float* w_gate   = (const float*)d_in[13];
    const float* w_up     = (const float*)d_in[14];
    const float* w_down   = (const float*)d_in[15];
    float* out = (float*)d_out;

    __half *xn, *q, *k, *v, *att, *ctx16, *gate, *up, *gu;
    float *h1, *h2;
    cudaGetSymbolAddress((void**)&xn,    g_xn);
    cudaGetSymbolAddress((void**)&q,     g_q);
    cudaGetSymbolAddress((void**)&k,     g_k);
    cudaGetSymbolAddress((void**)&v,     g_v);
    cudaGetSymbolAddress((void**)&att,   g_att);
    cudaGetSymbolAddress((void**)&ctx16, g_ctx);
    cudaGetSymbolAddress((void**)&h1,    g_h1);
    cudaGetSymbolAddress((void**)&h2,    g_h2);
    cudaGetSymbolAddress((void**)&gate,  g_gate);
    cudaGetSymbolAddress((void**)&up,    g_up);
    cudaGetSymbolAddress((void**)&gu,    g_gu);

    __half *wsaq, *wsak, *wsav, *wsao, *wcaq, *wcak, *wcav, *wcao, *wg, *wu, *wd;
    cudaGetSymbolAddress((void**)&wsaq, g_wt_saq);
    cudaGetSymbolAddress((void**)&wsak, g_wt_sak);
    cudaGetSymbolAddress((void**)&wsav, g_wt_sav);
    cudaGetSymbolAddress((void**)&wsao, g_wt_sao);
    cudaGetSymbolAddress((void**)&wcaq, g_wt_caq);
    cudaGetSymbolAddress((void**)&wcak, g_wt_cak);
    cudaGetSymbolAddress((void**)&wcav, g_wt_cav);
    cudaGetSymbolAddress((void**)&wcao, g_wt_cao);
    cudaGetSymbolAddress((void**)&wg,   g_wt_g);
    cudaGetSymbolAddress((void**)&wu,   g_wt_u);
    cudaGetSymbolAddress((void**)&wd,   g_wt_d);

    cudaFuncSetAttribute(attn_tc_kernel,
                         cudaFuncAttributeMaxDynamicSharedMemorySize, ATT_SMEM);
    cudaFuncSetAttribute(gemm_f16_kernel<0>,
                         cudaFuncAttributeMaxDynamicSharedMemorySize, GEMM_SMEM);
    cudaFuncSetAttribute(gemm_f16_kernel<1>,
                         cudaFuncAttributeMaxDynamicSharedMemorySize, GEMM_SMEM);

    const dim3 blk(256);
    const dim3 tgH(HDIM / 32, HDIM / 32);

    // ---- Weight conversion (transpose + fp16) ----
    tr16_kernel<<<tgH, blk>>>(sa_wq, wsaq, HDIM, HDIM);
    tr16_kernel<<<tgH, blk>>>(sa_wk, wsak, HDIM, HDIM);
    tr16_kernel<<<tgH, blk>>>(sa_wv, wsav, HDIM, HDIM);
    tr16_kernel<<<tgH, blk>>>(sa_wo, wsao, HDIM, HDIM);
    tr16_kernel<<<tgH, blk>>>(ca_wq, wcaq, HDIM, HDIM);
    tr16_kernel<<<tgH, blk>>>(ca_wk, wcak, HDIM, HDIM);
    tr16_kernel<<<tgH, blk>>>(ca_wv, wcav, HDIM, HDIM);
    tr16_kernel<<<tgH, blk>>>(ca_wo, wcao, HDIM, HDIM);
    tr16_kernel<<<dim3(ISZ / 32, HDIM / 32), blk>>>(w_gate, wg, HDIM, ISZ);
    tr16_kernel<<<dim3(ISZ / 32, HDIM / 32), blk>>>(w_up,   wu, HDIM, ISZ);
    tr16_kernel<<<dim3(HDIM / 32, ISZ / 32), blk>>>(w_down, wd, ISZ, HDIM);
    cvt16_kernel<<<(SQ * HDIM / 4 + 255) / 256, blk>>>(context, ctx16,
                                                       SQ * HDIM / 4);

    const dim3 gH1(HDIM / 64, SQ / 128, 1);   // 256
    const dim3 gH2(HDIM / 64, SQ / 128, 2);   // 512
    const dim3 gH3(HDIM / 64, SQ / 128, 3);   // 768
    const dim3 gI2(ISZ / 64,  SQ / 128, 2);   // 2048
    const dim3 gatt(SQ / 128, NH);            // 256

    // ---- Self-attention ----
    rmsnorm16_kernel<<<SQ, blk>>>(hidden, sa_norm, xn);
    gemm_f16_kernel<1><<<gH3, blk, GEMM_SMEM>>>(xn, wsaq, wsak, wsav, nullptr,
                                                q, k, v, SQ, HDIM, HDIM);
    attn_tc_kernel<<<gatt, blk, ATT_SMEM>>>(q, k, v, att);
    gemm_f16_kernel<0><<<gH1, blk, GEMM_SMEM>>>(att, wsao, wsao, wsao, hidden,
                                                h1, h1, h1, SQ, HDIM, HDIM);

    // ---- Cross-attention ----
    rmsnorm16_kernel<<<SQ, blk>>>(h1, ca_norm, xn);
    gemm_f16_kernel<1><<<gH1, blk, GEMM_SMEM>>>(xn, wcaq, wcaq, wcaq, nullptr,
                                                q, q, q, SQ, HDIM, HDIM);
    gemm_f16_kernel<1><<<gH2, blk, GEMM_SMEM>>>(ctx16, wcak, wcav, wcav,
                                                nullptr, k, v, v,
                                                SQ, HDIM, HDIM);
    attn_tc_kernel<<<gatt, blk, ATT_SMEM>>>(q, k, v, att);
    gemm_f16_kernel<0><<<gH1, blk, GEMM_SMEM>>>(att, wcao, wcao, wcao, h1,
                                                h2, h2, h2, SQ, HDIM, HDIM);

    // ---- MLP ----
    rmsnorm16_kernel<<<SQ, blk>>>(h2, mlp_norm, xn);
    gemm_f16_kernel<1><<<gI2, blk, GEMM_SMEM>>>(xn, wg, wu, wu, nullptr,
                                                gate, up, up, SQ, ISZ, HDIM);
    silu16_kernel<<<(SQ * ISZ / 2 + 255) / 256, blk>>>(gate, up, gu,
                                                       SQ * ISZ / 2);
    gemm_f16_kernel<0><<<gH1, blk, GEMM_SMEM>>>(gu, wd, wd, wd, h2,
                                                out, out, out, SQ, HDIM, ISZ);
}

// round 13
// speedup vs baseline: 1.5624x; 1.1483x over previous
#include <cuda_runtime.h>
#include <cuda_fp16.h>
#include <math.h>
#include <stdint.h>

// ---------------------------------------------------------------------------
// Problem dimensions
// ---------------------------------------------------------------------------
#define SQ   2048
#define HDIM 1024
#define NH   16
#define HD   64
#define ISZ  4096

// ---------------------------------------------------------------------------
// Scratch
// ---------------------------------------------------------------------------
__device__ __half g_xn [SQ * HDIM];
__device__ __half g_q  [SQ * HDIM];
__device__ __half g_k  [SQ * HDIM];
__device__ __half g_v  [SQ * HDIM];
__device__ __half g_att[SQ * HDIM];
__device__ __half g_ctx[SQ * HDIM];
__device__ float  g_h1 [SQ * HDIM];
__device__ float  g_h2 [SQ * HDIM];
__device__ __half g_gate[SQ * ISZ];
__device__ __half g_up  [SQ * ISZ];
__device__ __half g_gu  [SQ * ISZ];
// transposed fp16 weights [N][K]
__device__ __half g_wt_saq[HDIM * HDIM];
__device__ __half g_wt_sak[HDIM * HDIM];
__device__ __half g_wt_sav[HDIM * HDIM];
__device__ __half g_wt_sao[HDIM * HDIM];
__device__ __half g_wt_caq[HDIM * HDIM];
__device__ __half g_wt_cak[HDIM * HDIM];
__device__ __half g_wt_cav[HDIM * HDIM];
__device__ __half g_wt_cao[HDIM * HDIM];
__device__ __half g_wt_g  [ISZ * HDIM];
__device__ __half g_wt_u  [ISZ * HDIM];
__device__ __half g_wt_d  [HDIM * ISZ];

// ---------------------------------------------------------------------------
// Helpers
// ---------------------------------------------------------------------------
__device__ __forceinline__ void mma_f16(float* c, const uint32_t* a,
                                        uint32_t b0, uint32_t b1) {
    asm volatile(
        "mma.sync.aligned.m16n8k16.row.col.f32.f16.f16.f32 "
        "{%0,%1,%2,%3}, {%4,%5,%6,%7}, {%8,%9}, {%0,%1,%2,%3};"
        : "+f"(c[0]), "+f"(c[1]), "+f"(c[2]), "+f"(c[3])
        : "r"(a[0]), "r"(a[1]), "r"(a[2]), "r"(a[3]), "r"(b0), "r"(b1));
}

__device__ __forceinline__ void cp16(uint32_t smem_dst, const void* gsrc) {
    asm volatile("cp.async.ca.shared.global [%0], [%1], 16;\n"
                 :: "r"(smem_dst), "l"(gsrc));
}
__device__ __forceinline__ void cp_commit() {
    asm volatile("cp.async.commit_group;\n" ::: "memory");
}
template <int N>
__device__ __forceinline__ void cp_wait() {
    asm volatile("cp.async.wait_group %0;\n" :: "n"(N) : "memory");
}

__device__ __forceinline__ uint32_t h2u(half2 h) {
    return *reinterpret_cast<uint32_t*>(&h);
}

// ---------------------------------------------------------------------------
// Weight transpose + fp32->fp16
// ---------------------------------------------------------------------------
__global__ void __launch_bounds__(256) tr16_kernel(
    const float* __restrict__ in, __half* __restrict__ out, int K, int N)
{
    __shared__ float t[32][33];
    const int tx = threadIdx.x & 31;
    const int ty = threadIdx.x >> 5;
    const int n0 = blockIdx.x * 32;
    const int k0 = blockIdx.y * 32;
    #pragma unroll
    for (int j = 0; j < 4; ++j)
        t[ty + j * 8][tx] = in[(size_t)(k0 + ty + j * 8) * N + n0 + tx];
    __syncthreads();
    #pragma unroll
    for (int j = 0; j < 4; ++j)
        out[(size_t)(n0 + ty + j * 8) * K + k0 + tx] =
            __float2half_rn(t[tx][ty + j * 8]);
}

__global__ void __launch_bounds__(256) cvt16_kernel(
    const float* __restrict__ in, __half* __restrict__ out, int n4)
{
    const int i = blockIdx.x * blockDim.x + threadIdx.x;
    if (i >= n4) return;
    float4 v = ((const float4*)in)[i];
    ((half2*)out)[2 * i + 0] = __floats2half2_rn(v.x, v.y);
    ((half2*)out)[2 * i + 1] = __floats2half2_rn(v.z, v.w);
}

// ---------------------------------------------------------------------------
// RMSNorm: fp32 in -> fp16 out
// ---------------------------------------------------------------------------
__global__ void __launch_bounds__(256) rmsnorm16_kernel(
    const float* __restrict__ x, const float* __restrict__ w,
    __half* __restrict__ y)
{
    const int row = blockIdx.x;
    const int t   = threadIdx.x;
    float4 vx = ((const float4*)(x + (size_t)row * HDIM))[t];
    float s = vx.x*vx.x + vx.y*vx.y + vx.z*vx.z + vx.w*vx.w;
    #pragma unroll
    for (int o = 16; o; o >>= 1) s += __shfl_xor_sync(0xffffffffu, s, o);

    __shared__ float red[8];
    __shared__ float s_inv;
    if ((t & 31) == 0) red[t >> 5] = s;
    __syncthreads();
    if (t == 0) {
        float tot = 0.f;
        #pragma unroll
        for (int i = 0; i < 8; ++i) tot += red[i];
        s_inv = 1.0f / sqrtf(tot * (1.0f / (float)HDIM) + 1e-6f);
    }
    __syncthreads();
    const float r = s_inv;
    float4 vw = ((const float4*)w)[t];
    half2* yrow = (half2*)(y + (size_t)row * HDIM);
    yrow[2 * t + 0] = __floats2half2_rn(vx.x * r * vw.x, vx.y * r * vw.y);
    yrow[2 * t + 1] = __floats2half2_rn(vx.z * r * vw.z, vx.w * r * vw.w);
}

// ---------------------------------------------------------------------------
// fp16 mma.sync GEMM (m16n8k16), 3-stage cp.async pipeline (R12, proven).
// ---------------------------------------------------------------------------
#define RS16  20
#define A16_STG (128 * RS16)
#define B16_STG (64 * RS16)
#define GEMM_SMEM ((3 * A16_STG + 3 * B16_STG) * 4)

template <int OUTF16>
__global__ void __launch_bounds__(256, 2) gemm_f16_kernel(
    const __half* __restrict__ A,
    const __half* __restrict__ B0, const __half* __restrict__ B1,
    const __half* __restrict__ B2,
    const float* __restrict__ R,
    void* __restrict__ C0, void* __restrict__ C1, void* __restrict__ C2,
    int M, int N, int K)
{
    extern __shared__ uint32_t smw[];
    uint32_t* As = smw;
    uint32_t* Bs = smw + 3 * A16_STG;

    const __half* B = (blockIdx.z == 0) ? B0 : (blockIdx.z == 1 ? B1 : B2);
    void*         C = (blockIdx.z == 0) ? C0 : (blockIdx.z == 1 ? C1 : C2);

    const int tid  = threadIdx.x;
    const int lane = tid & 31;
    const int wid  = tid >> 5;
    const int g    = lane >> 2;
    const int tig  = lane & 3;
    const int wm   = (wid >> 1) * 32;
    const int wn   = (wid & 1) * 32;
    const int bm   = blockIdx.y * 128;
    const int bn   = blockIdx.x * 64;

    float acc[2][4][4];
    #pragma unroll
    for (int mt = 0; mt < 2; ++mt)
        #pragma unroll
        for (int nt = 0; nt < 4; ++nt)
            #pragma unroll
            for (int e = 0; e < 4; ++e) acc[mt][nt][e] = 0.f;

    const int niter = K >> 5;

    auto issue = [&](int i, int s) {
        const int k0 = i << 5;
        #pragma unroll
        for (int it = 0; it < 2; ++it) {
            const int chunk = tid + it * 256;
            const int r = chunk >> 2;
            const int c = chunk & 3;
            uint32_t dst = (uint32_t)__cvta_generic_to_shared(
                &As[s * A16_STG + r * RS16 + 4 * c]);
            cp16(dst, A + (size_t)(bm + r) * K + k0 + 8 * c);
        }
        {
            const int r = tid >> 2;
            const int c = tid & 3;
            uint32_t dst = (uint32_t)__cvta_generic_to_shared(
                &Bs[s * B16_STG + r * RS16 + 4 * c]);
            cp16(dst, B + (size_t)(bn + r) * K + k0 + 8 * c);
        }
    };

    issue(0, 0);
    cp_commit();
    if (niter > 1) issue(1, 1);
    cp_commit();

    for (int i = 0; i < niter; ++i) {
        const int s = i - (i / 3) * 3;
        cp_wait<1>();
        __syncthreads();

        const uint32_t* Ast = As + s * A16_STG;
        const uint32_t* Bst = Bs + s * B16_STG;

        uint32_t af[2][2][4];
        uint32_t bf[2][4][2];
        #pragma unroll
        for (int kt = 0; kt < 2; ++kt) {
            #pragma unroll
            for (int nt = 0; nt < 4; ++nt) {
                const int base = (wn + nt * 8 + g) * RS16 + kt * 8 + tig;
                bf[kt][nt][0] = Bst[base];
                bf[kt][nt][1] = Bst[base + 4];
            }
            #pragma unroll
            for (int mt = 0; mt < 2; ++mt) {
                const int b0 = (wm + mt * 16 + g) * RS16 + kt * 8 + tig;
                af[kt][mt][0] = Ast[b0];
                af[kt][mt][1] = Ast[b0 + 8 * RS16];
                af[kt][mt][2] = Ast[b0 + 4];
                af[kt][mt][3] = Ast[b0 + 8 * RS16 + 4];
            }
        }

        #pragma unroll
        for (int kt = 0; kt < 2; ++kt)
            #pragma unroll
            for (int mt = 0; mt < 2; ++mt)
                #pragma unroll
                for (int nt = 0; nt < 4; ++nt)
                    mma_f16(acc[mt][nt], af[kt][mt],
                            bf[kt][nt][0], bf[kt][nt][1]);

        __syncthreads();
        const int j = i + 2;
        if (j < niter) issue(j, j - (j / 3) * 3);
        cp_commit();
    }

    #pragma unroll
    for (int mt = 0; mt < 2; ++mt) {
        const int r0 = bm + wm + mt * 16 + g;
        const int r1 = r0 + 8;
        #pragma unroll
        for (int nt = 0; nt < 4; ++nt) {
            const int col = bn + wn + nt * 8 + 2 * tig;
            if (OUTF16) {
                __half* Ch = (__half*)C;
                *(half2*)(Ch + (size_t)r0 * N + col) =
                    __floats2half2_rn(acc[mt][nt][0], acc[mt][nt][1]);
                *(half2*)(Ch + (size_t)r1 * N + col) =
                    __floats2half2_rn(acc[mt][nt][2], acc[mt][nt][3]);
            } else {
                float* Cf = (float*)C;
                float2 v0 = make_float2(acc[mt][nt][0], acc[mt][nt][1]);
                float2 v1 = make_float2(acc[mt][nt][2], acc[mt][nt][3]);
                if (R) {
                    float2 a0 = *(const float2*)(R + (size_t)r0 * N + col);
                    float2 a1 = *(const float2*)(R + (size_t)r1 * N + col);
                    v0.x += a0.x; v0.y += a0.y;
                    v1.x += a1.x; v1.y += a1.y;
                }
                *(float2*)(Cf + (size_t)r0 * N + col) = v0;
                *(float2*)(Cf + (size_t)r1 * N + col) = v1;
            }
        }
    }
}

// ---------------------------------------------------------------------------
// Flash attention, fp16 mma core (m16n8k16). fp16 in / fp16 out.
// Block = 128 q-rows x 1 head, 8 warps; each warp 16 q-rows x 64 kv.
// Qs/Ks: [row][d] halves, row stride 36 words (64 halves + pad).
// Vt: j-pair packed [d][j/2], stride 36 words.
// P C-fragment maps natively to PV A-fragment (no shuffles).
// ---------------------------------------------------------------------------
#define AS16 36
#define ATT_SMEM ((128 * AS16 + 64 * AS16 + 64 * AS16) * 4)

__global__ void __launch_bounds__(256) attn_f16_kernel(
    const __half* __restrict__ Qg, const __half* __restrict__ Kg,
    const __half* __restrict__ Vg, __half* __restrict__ Og)
{
    extern __shared__ uint32_t sm[];
    uint32_t* Qs = sm;                       // [128][AS16]
    uint32_t* Ks = sm + 128 * AS16;          // [64][AS16]
    uint32_t* Vt = sm + 192 * AS16;          // [64 d][AS16] (j-pairs)

    const int tid  = threadIdx.x;
    const int lane = tid & 31;
    const int wid  = tid >> 5;
    const int g    = lane >> 2;
    const int tig  = lane & 3;
    const int i0   = blockIdx.x * 128;
    const int hoff = blockIdx.y * HD;
    const int qrow = wid * 16;

    // Q: straight cp.async copy (scale folded into S post-MMA)
    #pragma unroll
    for (int it = 0; it < 4; ++it) {
        const int chunk = tid + it * 256;
        const int r = chunk >> 3;
        const int c = chunk & 7;
        uint32_t dst = (uint32_t)__cvta_generic_to_shared(&Qs[r * AS16 + 4 * c]);
        cp16(dst, Qg + (size_t)(i0 + r) * HDIM + hoff + 8 * c);
    }
    cp_commit();

    float m0 = -1e30f, m1 = -1e30f;
    float l0 = 0.f, l1 = 0.f;
    float o[8][4];
    #pragma unroll
    for (int nt = 0; nt < 8; ++nt)
        #pragma unroll
        for (int e = 0; e < 4; ++e) o[nt][e] = 0.f;

    for (int j0 = 0; j0 < SQ; j0 += 64) {
        __syncthreads();   // prior-tile consumers done
        // K: straight cp.async copy [j][d]
        #pragma unroll
        for (int it = 0; it < 2; ++it) {
            const int chunk = tid + it * 256;
            const int r = chunk >> 3;
            const int c = chunk & 7;
            uint32_t dst = (uint32_t)__cvta_generic_to_shared(
                &Ks[r * AS16 + 4 * c]);
            cp16(dst, Kg + (size_t)(j0 + r) * HDIM + hoff + 8 * c);
        }
        cp_commit();
        // V: manual transpose into j-pair-packed [d][j/2]
        __half* Vth = (__half*)Vt;
        #pragma unroll
        for (int it = 0; it < 4; ++it) {
            const int r  = it * 16 + (tid >> 4);      // j
            const int c4 = (tid & 15) << 2;           // d base
            const __half* vp = Vg + (size_t)(j0 + r) * HDIM + hoff + c4;
            half2 v0 = *(const half2*)(vp);
            half2 v1 = *(const half2*)(vp + 2);
            const int w = (r >> 1) * 2 + (r & 1);     // half index within pair word
            Vth[((c4 + 0) * AS16 + (r >> 1)) * 2 + (r & 1)] = __low2half(v0);
            Vth[((c4 + 1) * AS16 + (r >> 1)) * 2 + (r & 1)] = __high2half(v0);
            Vth[((c4 + 2) * AS16 + (r >> 1)) * 2 + (r & 1)] = __low2half(v1);
            Vth[((c4 + 3) * AS16 + (r >> 1)) * 2 + (r & 1)] = __high2half(v1);
            (void)w;
        }
        cp_wait<0>();
        __syncthreads();

        // ---- S = Q K^T (fp16 mma, fp32 acc) ----
        float s[8][4];
        #pragma unroll
        for (int nt = 0; nt < 8; ++nt)
            #pragma unroll
            for (int e = 0; e < 4; ++e) s[nt][e] = 0.f;

        #pragma unroll
        for (int kt = 0; kt < 4; ++kt) {
            uint32_t a[4];
            const int base = (qrow + g) * AS16 + kt * 8 + tig;
            a[0] = Qs[base];
            a[1] = Qs[base + 8 * AS16];
            a[2] = Qs[base + 4];
            a[3] = Qs[base + 8 * AS16 + 4];
            #pragma unroll
            for (int nt = 0; nt < 8; ++nt) {
                const int jb = (nt * 8 + g) * AS16 + kt * 8 + tig;
                mma_f16(s[nt], a, Ks[jb], Ks[jb + 4]);
            }
        }
        // fold 1/sqrt(HD) scale
        #pragma unroll
        for (int nt = 0; nt < 8; ++nt)
            #pragma unroll
            for (int e = 0; e < 4; ++e) s[nt][e] *= 0.125f;

        // ---- Online softmax (rows g -> regs 0,1; g+8 -> regs 2,3) ----
        float mt0 = -1e30f, mt1 = -1e30f;
        #pragma unroll
        for (int nt = 0; nt < 8; ++nt) {
            mt0 = fmaxf(mt0, fmaxf(s[nt][0], s[nt][1]));
            mt1 = fmaxf(mt1, fmaxf(s[nt][2], s[nt][3]));
        }
        mt0 = fmaxf(mt0, __shfl_xor_sync(0xffffffffu, mt0, 1));
        mt0 = fmaxf(mt0, __shfl_xor_sync(0xffffffffu, mt0, 2));
        mt1 = fmaxf(mt1, __shfl_xor_sync(0xffffffffu, mt1, 1));
        mt1 = fmaxf(mt1, __shfl_xor_sync(0xffffffffu, mt1, 2));

        const float mn0 = fmaxf(m0, mt0);
        const float mn1 = fmaxf(m1, mt1);
        const float c0 = __expf(m0 - mn0);
        const float c1 = __expf(m1 - mn1);
        m0 = mn0; m1 = mn1;

        float ps0 = 0.f, ps1 = 0.f;
        #pragma unroll
        for (int nt = 0; nt < 8; ++nt) {
            s[nt][0] = __expf(s[nt][0] - mn0);
            s[nt][1] = __expf(s[nt][1] - mn0);
            s[nt][2] = __expf(s[nt][2] - mn1);
            s[nt][3] = __expf(s[nt][3] - mn1);
            ps0 += s[nt][0] + s[nt][1];
            ps1 += s[nt][2] + s[nt][3];
        }
        ps0 += __shfl_xor_sync(0xffffffffu, ps0, 1);
        ps0 += __shfl_xor_sync(0xffffffffu, ps0, 2);
        ps1 += __shfl_xor_sync(0xffffffffu, ps1, 1);
        ps1 += __shfl_xor_sync(0xffffffffu, ps1, 2);
        l0 = l0 * c0 + ps0;
        l1 = l1 * c1 + ps1;

        #pragma unroll
        for (int nt = 0; nt < 8; ++nt) {
            o[nt][0] *= c0; o[nt][1] *= c0;
            o[nt][2] *= c1; o[nt][3] *= c1;
        }

        // ---- O += P V : C-fragment maps natively to A-fragment ----
        #pragma unroll
        for (int jt = 0; jt < 4; ++jt) {
            uint32_t a[4];
            a[0] = h2u(__floats2half2_rn(s[2 * jt][0],     s[2 * jt][1]));
            a[1] = h2u(__floats2half2_rn(s[2 * jt][2],     s[2 * jt][3]));
            a[2] = h2u(__floats2half2_rn(s[2 * jt + 1][0], s[2 * jt + 1][1]));
            a[3] = h2u(__floats2half2_rn(s[2 * jt + 1][2], s[2 * jt + 1][3]));
            #pragma unroll
            for (int nt = 0; nt < 8; ++nt) {
                const int vb = (nt * 8 + g) * AS16 + jt * 8 + tig;
                mma_f16(o[nt], a, Vt[vb], Vt[vb + 4]);
            }
        }
    }

    const float i0f = 1.0f / l0;
    const float i1f = 1.0f / l1;
    const int r0 = i0 + qrow + g;
    const int r1 = r0 + 8;
    #pragma unroll
    for (int nt = 0; nt < 8; ++nt) {
        const int col = hoff + nt * 8 + 2 * tig;
        *(half2*)(Og + (size_t)r0 * HDIM + col) =
            __floats2half2_rn(o[nt][0] * i0f, o[nt][1] * i0f);
        *(half2*)(Og + (size_t)r1 * HDIM + col) =
            __floats2half2_rn(o[nt][2] * i1f, o[nt][3] * i1f);
    }
}

// ---------------------------------------------------------------------------
// SwiGLU elementwise: fp16 in/out
// ---------------------------------------------------------------------------
__global__ void __launch_bounds__(256) silu16_kernel(
    const __half* __restrict__ g, const __half* __restrict__ u,
    __half* __restrict__ out, int n2)
{
    const int i = blockIdx.x * blockDim.x + threadIdx.x;
    if (i >= n2) return;
    float2 gf = __half22float2(((const half2*)g)[i]);
    float2 uf = __half22float2(((const half2*)u)[i]);
    float ox = gf.x * (1.0f / (1.0f + __expf(-gf.x))) * uf.x;
    float oy = gf.y * (1.0f / (1.0f + __expf(-gf.y))) * uf.y;
    ((half2*)out)[i] = __floats2half2_rn(ox, oy);
}

// ---------------------------------------------------------------------------
// Launch sequence
// ---------------------------------------------------------------------------
extern "C" void kernel_launch(void* const* d_in, const int* in_sizes, int n_in,
                              void* d_out, int out_size)
{
    (void)in_sizes; (void)n_in; (void)out_size;

    const float* hidden   = (const float*)d_in[0];
    const float* context  = (const float*)d_in[1];
    const float* sa_norm  = (const float*)d_in[2];
    const float* sa_wq    = (const float*)d_in[3];
    const float* sa_wk    = (const float*)d_in[4];
    const float* sa_wv    = (const float*)d_in[5];
    const float* sa_wo    = (const float*)d_in[6];
    const float* ca_norm  = (const float*)d_in[7];
    const float* ca_wq    = (const float*)d_in[8];
    const float* ca_wk    = (const float*)d_in[9];
    const float* ca_wv    = (const float*)d_in[10];
    const float* ca_wo    = (const float*)d_in[11];
    const float* mlp_norm = (const float*)d_in[12];
    const float* w_gate   = (const float*)d_in[13];
    const float* w_up     = (const float*)d_in[14];
    const float* w_down   = (const float*)d_in[15];
    float* out = (float*)d_out;

    __half *xn, *q, *k, *v, *att, *ctx16, *gate, *up, *gu;
    float *h1, *h2;
    cudaGetSymbolAddress((void**)&xn,    g_xn);
    cudaGetSymbolAddress((void**)&q,     g_q);
    cudaGetSymbolAddress((void**)&k,     g_k);
    cudaGetSymbolAddress((void**)&v,     g_v);
    cudaGetSymbolAddress((void**)&att,   g_att);
    cudaGetSymbolAddress((void**)&ctx16, g_ctx);
    cudaGetSymbolAddress((void**)&h1,    g_h1);
    cudaGetSymbolAddress((void**)&h2,    g_h2);
    cudaGetSymbolAddress((void**)&gate,  g_gate);
    cudaGetSymbolAddress((void**)&up,    g_up);
    cudaGetSymbolAddress((void**)&gu,    g_gu);

    __half *wsaq, *wsak, *wsav, *wsao, *wcaq, *wcak, *wcav, *wcao, *wg, *wu, *wd;
    cudaGetSymbolAddress((void**)&wsaq, g_wt_saq);
    cudaGetSymbolAddress((void**)&wsak, g_wt_sak);
    cudaGetSymbolAddress((void**)&wsav, g_wt_sav);
    cudaGetSymbolAddress((void**)&wsao, g_wt_sao);
    cudaGetSymbolAddress((void**)&wcaq, g_wt_caq);
    cudaGetSymbolAddress((void**)&wcak, g_wt_cak);
    cudaGetSymbolAddress((void**)&wcav, g_wt_cav);
    cudaGetSymbolAddress((void**)&wcao, g_wt_cao);
    cudaGetSymbolAddress((void**)&wg,   g_wt_g);
    cudaGetSymbolAddress((void**)&wu,   g_wt_u);
    cudaGetSymbolAddress((void**)&wd,   g_wt_d);

    cudaFuncSetAttribute(attn_f16_kernel,
                         cudaFuncAttributeMaxDynamicSharedMemorySize, ATT_SMEM);
    cudaFuncSetAttribute(gemm_f16_kernel<0>,
                         cudaFuncAttributeMaxDynamicSharedMemorySize, GEMM_SMEM);
    cudaFuncSetAttribute(gemm_f16_kernel<1>,
                         cudaFuncAttributeMaxDynamicSharedMemorySize, GEMM_SMEM);

    const dim3 blk(256);
    const dim3 tgH(HDIM / 32, HDIM / 32);

    // ---- Weight conversion (transpose + fp16) ----
    tr16_kernel<<<tgH, blk>>>(sa_wq, wsaq, HDIM, HDIM);
    tr16_kernel<<<tgH, blk>>>(sa_wk, wsak, HDIM, HDIM);
    tr16_kernel<<<tgH, blk>>>(sa_wv, wsav, HDIM, HDIM);
    tr16_kernel<<<tgH, blk>>>(sa_wo, wsao, HDIM, HDIM);
    tr16_kernel<<<tgH, blk>>>(ca_wq, wcaq, HDIM, HDIM);
    tr16_kernel<<<tgH, blk>>>(ca_wk, wcak, HDIM, HDIM);
    tr16_kernel<<<tgH, blk>>>(ca_wv, wcav, HDIM, HDIM);
    tr16_kernel<<<tgH, blk>>>(ca_wo, wcao, HDIM, HDIM);
    tr16_kernel<<<dim3(ISZ / 32, HDIM / 32), blk>>>(w_gate, wg, HDIM, ISZ);
    tr16_kernel<<<dim3(ISZ / 32, HDIM / 32), blk>>>(w_up,   wu, HDIM, ISZ);
    tr16_kernel<<<dim3(HDIM / 32, ISZ / 32), blk>>>(w_down, wd, ISZ, HDIM);
    cvt16_kernel<<<(SQ * HDIM / 4 + 255) / 256, blk>>>(context, ctx16,
                                                       SQ * HDIM / 4);

    const dim3 gH1(HDIM / 64, SQ / 128, 1);
    const dim3 gH2(HDIM / 64, SQ / 128, 2);
    const dim3 gH3(HDIM / 64, SQ / 128, 3);
    const dim3 gI2(ISZ / 64,  SQ / 128, 2);
    const dim3 gatt(SQ / 128, NH);

    // ---- Self-attention ----
    rmsnorm16_kernel<<<SQ, blk>>>(hidden, sa_norm, xn);
    gemm_f16_kernel<1><<<gH3, blk, GEMM_SMEM>>>(xn, wsaq, wsak, wsav, nullptr,
                                                q, k, v, SQ, HDIM, HDIM);
    attn_f16_kernel<<<gatt, blk, ATT_SMEM>>>(q, k, v, att);
    gemm_f16_kernel<0><<<gH1, blk, GEMM_SMEM>>>(att, wsao, wsao, wsao, hidden,
                                                h1, h1, h1, SQ, HDIM, HDIM);

    // ---- Cross-attention ----
    rmsnorm16_kernel<<<SQ, blk>>>(h1, ca_norm, xn);
    gemm_f16_kernel<1><<<gH1, blk, GEMM_SMEM>>>(xn, wcaq, wcaq, wcaq, nullptr,
                                                q, q, q, SQ, HDIM, HDIM);
    gemm_f16_kernel<1><<<gH2, blk, GEMM_SMEM>>>(ctx16, wcak, wcav, wcav,
                                                nullptr, k, v, v,
                                                SQ, HDIM, HDIM);
    attn_f16_kernel<<<gatt, blk, ATT_SMEM>>>(q, k, v, att);
    gemm_f16_kernel<0><<<gH1, blk, GEMM_SMEM>>>(att, wcao, wcao, wcao, h1,
                                                h2, h2, h2, SQ, HDIM, HDIM);

    // ---- MLP ----
    rmsnorm16_kernel<<<SQ, blk>>>(h2, mlp_norm, xn);
    gemm_f16_kernel<1><<<gI2, blk, GEMM_SMEM>>>(xn, wg, wu, wu, nullptr,
                                                gate, up, up, SQ, ISZ, HDIM);
    silu16_kernel<<<(SQ * ISZ / 2 + 255) / 256, blk>>>(gate, up, gu,
                                                       SQ * ISZ / 2);
    gemm_f16_kernel<0><<<gH1, blk, GEMM_SMEM>>>(gu, wd, wd, wd, h2,
                                                out, out, out, SQ, HDIM, ISZ);
}